// round 1
// baseline (speedup 1.0000x reference)
#include <cuda_runtime.h>

// Problem constants
#define BATCH   2
#define NVIEW   6
#define XD      8
#define YD      8
#define W1D     8
#define W2D     8
#define DIM     128
#define HEADS   4
#define DHEAD   32
#define HDIM    128          // HEADS*DHEAD
#define LWIN    64           // X*Y
#define QTOK    384          // N*W1*W2
#define NBL     128          // BATCH*LWIN
#define TOKENS  49152        // BATCH*LWIN*QTOK
#define R2ROWS  8192         // BATCH*LWIN*W1*W2 (post-mean rows)
#define EPS     1e-5f

// Scratch (device globals; no allocation allowed)
__device__ float g_qp[TOKENS * HDIM];
__device__ float g_kp[TOKENS * HDIM];
__device__ float g_vp[TOKENS * HDIM];
__device__ float g_at[TOKENS * HDIM];

// ---------------------------------------------------------------------------
// Kernel 1: fold + LayerNorm + projection GEMM for q/k/v.
// grid = (768, 3), block = 256. Tile: 64 tokens x 128 outputs, K=128.
// smem: Xs 64*128 + Ws 128*128 = 96 KB
// ---------------------------------------------------------------------------
__global__ __launch_bounds__(256) void ln_proj_kernel(
    const float* __restrict__ q, const float* __restrict__ k, const float* __restrict__ v,
    const float* __restrict__ lnq_g, const float* __restrict__ lnq_b,
    const float* __restrict__ lnk_g, const float* __restrict__ lnk_b,
    const float* __restrict__ lnv_g, const float* __restrict__ lnv_b,
    const float* __restrict__ wq, const float* __restrict__ bq,
    const float* __restrict__ wk, const float* __restrict__ bk,
    const float* __restrict__ wv, const float* __restrict__ bv)
{
    extern __shared__ float sm[];
    float* Xs = sm;                 // 64*128
    float* Ws = sm + 64 * 128;      // 128*128

    const float* src; const float* gam; const float* bet;
    const float* W; const float* bias; float* dst;
    int mat = blockIdx.y;
    if (mat == 0)      { src = q; gam = lnq_g; bet = lnq_b; W = wq; bias = bq; dst = g_qp; }
    else if (mat == 1) { src = k; gam = lnk_g; bet = lnk_b; W = wk; bias = bk; dst = g_kp; }
    else               { src = v; gam = lnv_g; bet = lnv_b; W = wv; bias = bv; dst = g_vp; }

    int tid  = threadIdx.x;
    int warp = tid >> 5;
    int lane = tid & 31;
    int row0 = blockIdx.x * 64;

    // Load weight matrix into shared (16384 floats as float4)
    for (int i = tid; i < 128 * 32; i += 256)
        ((float4*)Ws)[i] = ((const float4*)W)[i];

    // LayerNorm 64 tokens: each warp normalizes one token per iteration
    float4 gg  = ((const float4*)gam)[lane];
    float4 bb4 = ((const float4*)bet)[lane];
    for (int it = 0; it < 8; ++it) {
        int rloc = it * 8 + warp;
        int r = row0 + rloc;
        // decode token row -> source offset in (B,N,X,Y,W1,W2,D)
        int bIdx = r / (LWIN * QTOK);
        int rem  = r % (LWIN * QTOK);
        int l = rem / QTOK;
        int t = rem % QTOK;
        int x = l >> 3, y = l & 7;
        int n = t / 64; int w12 = t & 63; int w1 = w12 >> 3, w2 = w12 & 7;
        int srcOff = (((((bIdx * NVIEW + n) * XD + x) * YD + y) * W1D + w1) * W2D + w2) * DIM;

        float4 xv = ((const float4*)(src + srcOff))[lane];
        float s  = xv.x + xv.y + xv.z + xv.w;
        float ss = xv.x * xv.x + xv.y * xv.y + xv.z * xv.z + xv.w * xv.w;
        #pragma unroll
        for (int o = 16; o; o >>= 1) {
            s  += __shfl_xor_sync(0xffffffffu, s,  o);
            ss += __shfl_xor_sync(0xffffffffu, ss, o);
        }
        float mu  = s * (1.0f / 128.0f);
        float var = ss * (1.0f / 128.0f) - mu * mu;
        float rs  = rsqrtf(var + EPS);
        float4 ov;
        ov.x = (xv.x - mu) * rs * gg.x + bb4.x;
        ov.y = (xv.y - mu) * rs * gg.y + bb4.y;
        ov.z = (xv.z - mu) * rs * gg.z + bb4.z;
        ov.w = (xv.w - mu) * rs * gg.w + bb4.w;
        ((float4*)(Xs + rloc * 128))[lane] = ov;
    }
    __syncthreads();

    // GEMM: 8 rows x 4 cols per thread. warp ti owns rows ti*8..+7 (broadcast LDS)
    int ti = warp;
    int cj = lane;
    float acc[8][4];
    #pragma unroll
    for (int i = 0; i < 8; ++i) { acc[i][0]=0.f; acc[i][1]=0.f; acc[i][2]=0.f; acc[i][3]=0.f; }

    const float4* Ws4 = (const float4*)Ws;
    #pragma unroll 8
    for (int kk = 0; kk < 128; ++kk) {
        float4 wv = Ws4[kk * 32 + cj];
        #pragma unroll
        for (int i = 0; i < 8; ++i) {
            float xv = Xs[(ti * 8 + i) * 128 + kk];
            acc[i][0] += xv * wv.x;
            acc[i][1] += xv * wv.y;
            acc[i][2] += xv * wv.z;
            acc[i][3] += xv * wv.w;
        }
    }

    float4 bsv = ((const float4*)bias)[cj];
    #pragma unroll
    for (int i = 0; i < 8; ++i) {
        int r = row0 + ti * 8 + i;
        float4 o;
        o.x = acc[i][0] + bsv.x;
        o.y = acc[i][1] + bsv.y;
        o.z = acc[i][2] + bsv.z;
        o.w = acc[i][3] + bsv.w;
        ((float4*)(dst + (size_t)r * 128))[cj] = o;
    }
}

// ---------------------------------------------------------------------------
// Kernel 2: attention per (b,l,head). grid = 512, block = 384 (1 thread = 1 q row)
// smem: Ks 384*32 + Vs 384*32 = 96 KB. All K/V smem reads warp-uniform (broadcast)
// ---------------------------------------------------------------------------
__global__ __launch_bounds__(384) void attn_kernel()
{
    extern __shared__ float sm[];
    float* Ks = sm;               // 384*32
    float* Vs = sm + 384 * 32;    // 384*32

    int bl = blockIdx.x >> 2;     // 0..127 : b*L + l
    int m  = blockIdx.x & 3;      // head
    size_t base = (size_t)bl * QTOK * 128 + m * 32;

    int tid = threadIdx.x;

    // Load K,V tiles (head slice) to smem
    for (int i = tid; i < QTOK * 8; i += 384) {
        int row = i >> 3, c = i & 7;
        ((float4*)Ks)[row * 8 + c] = ((const float4*)(g_kp + base + (size_t)row * 128))[c];
        ((float4*)Vs)[row * 8 + c] = ((const float4*)(g_vp + base + (size_t)row * 128))[c];
    }
    __syncthreads();

    // q row in registers, pre-scaled
    const float scale = 0.1767766952966369f;  // 1/sqrt(32)
    float qr[32];
    #pragma unroll
    for (int c = 0; c < 8; ++c) {
        float4 t4 = ((const float4*)(g_qp + base + (size_t)tid * 128))[c];
        qr[c*4+0] = t4.x * scale; qr[c*4+1] = t4.y * scale;
        qr[c*4+2] = t4.z * scale; qr[c*4+3] = t4.w * scale;
    }

    float o[32];
    #pragma unroll
    for (int d = 0; d < 32; ++d) o[d] = 0.f;
    float mval = -1e30f, lsum = 0.f;

    for (int kc = 0; kc < QTOK; kc += 8) {
        float s[8];
        #pragma unroll
        for (int i = 0; i < 8; ++i) {
            const float* kr = Ks + (kc + i) * 32;
            float a = 0.f;
            #pragma unroll
            for (int d = 0; d < 32; ++d) a += qr[d] * kr[d];
            s[i] = a;
        }
        float cm = s[0];
        #pragma unroll
        for (int i = 1; i < 8; ++i) cm = fmaxf(cm, s[i]);
        float mnew = fmaxf(mval, cm);
        float corr = __expf(mval - mnew);
        lsum *= corr;
        #pragma unroll
        for (int d = 0; d < 32; ++d) o[d] *= corr;
        #pragma unroll
        for (int i = 0; i < 8; ++i) {
            float p = __expf(s[i] - mnew);
            lsum += p;
            const float* vr = Vs + (kc + i) * 32;
            #pragma unroll
            for (int d = 0; d < 32; ++d) o[d] += p * vr[d];
        }
        mval = mnew;
    }

    float inv = 1.0f / lsum;
    #pragma unroll
    for (int c = 0; c < 8; ++c) {
        float4 t4;
        t4.x = o[c*4+0] * inv; t4.y = o[c*4+1] * inv;
        t4.z = o[c*4+2] * inv; t4.w = o[c*4+3] * inv;
        ((float4*)(g_at + base + (size_t)tid * 128))[c] = t4;
    }
}

// ---------------------------------------------------------------------------
// Kernel 3: fused mean-over-views (linear, commutes with projection) +
// output projection + bias + skip. grid = 128, block = 256. Tile 64x128.
// ---------------------------------------------------------------------------
__global__ __launch_bounds__(256) void out_proj_kernel(
    const float* __restrict__ wp, const float* __restrict__ bp,
    const float* __restrict__ skip, float* __restrict__ out)
{
    extern __shared__ float sm[];
    float* Xs = sm;                 // 64*128
    float* Ws = sm + 64 * 128;      // 128*128

    int tid  = threadIdx.x;
    int row0 = blockIdx.x * 64;

    for (int i = tid; i < 128 * 32; i += 256)
        ((float4*)Ws)[i] = ((const float4*)wp)[i];

    // Load Xs = mean over n of attention output (rows indexed (b,l,w1*8+w2))
    for (int i = tid; i < 64 * 32; i += 256) {
        int rloc = i >> 5, c = i & 31;
        int r2 = row0 + rloc;
        int bl = r2 >> 6;
        int w  = r2 & 63;
        float4 a; a.x = 0.f; a.y = 0.f; a.z = 0.f; a.w = 0.f;
        #pragma unroll
        for (int n = 0; n < NVIEW; ++n) {
            float4 t = ((const float4*)(g_at + ((size_t)(bl * QTOK + n * 64 + w)) * 128))[c];
            a.x += t.x; a.y += t.y; a.z += t.z; a.w += t.w;
        }
        const float invn = 1.0f / 6.0f;
        a.x *= invn; a.y *= invn; a.z *= invn; a.w *= invn;
        ((float4*)Xs)[rloc * 32 + c] = a;
    }
    __syncthreads();

    int ti = tid >> 5;
    int cj = tid & 31;
    float acc[8][4];
    #pragma unroll
    for (int i = 0; i < 8; ++i) { acc[i][0]=0.f; acc[i][1]=0.f; acc[i][2]=0.f; acc[i][3]=0.f; }

    const float4* Ws4 = (const float4*)Ws;
    #pragma unroll 8
    for (int kk = 0; kk < 128; ++kk) {
        float4 wv = Ws4[kk * 32 + cj];
        #pragma unroll
        for (int i = 0; i < 8; ++i) {
            float xv = Xs[(ti * 8 + i) * 128 + kk];
            acc[i][0] += xv * wv.x;
            acc[i][1] += xv * wv.y;
            acc[i][2] += xv * wv.z;
            acc[i][3] += xv * wv.w;
        }
    }

    float4 bsv = ((const float4*)bp)[cj];
    #pragma unroll
    for (int i = 0; i < 8; ++i) {
        int r = row0 + ti * 8 + i;
        float4 sk = ((const float4*)(skip + (size_t)r * 128))[cj];
        float4 o;
        o.x = acc[i][0] + bsv.x + sk.x;
        o.y = acc[i][1] + bsv.y + sk.y;
        o.z = acc[i][2] + bsv.z + sk.z;
        o.w = acc[i][3] + bsv.w + sk.w;
        ((float4*)(out + (size_t)r * 128))[cj] = o;
    }
}

// ---------------------------------------------------------------------------
extern "C" void kernel_launch(void* const* d_in, const int* in_sizes, int n_in,
                              void* d_out, int out_size)
{
    const float* q     = (const float*)d_in[0];
    const float* k     = (const float*)d_in[1];
    const float* v     = (const float*)d_in[2];
    const float* skip  = (const float*)d_in[3];
    const float* lnq_g = (const float*)d_in[4];
    const float* lnq_b = (const float*)d_in[5];
    const float* lnk_g = (const float*)d_in[6];
    const float* lnk_b = (const float*)d_in[7];
    const float* lnv_g = (const float*)d_in[8];
    const float* lnv_b = (const float*)d_in[9];
    const float* wq    = (const float*)d_in[10];
    const float* bq    = (const float*)d_in[11];
    const float* wk    = (const float*)d_in[12];
    const float* bk    = (const float*)d_in[13];
    const float* wv    = (const float*)d_in[14];
    const float* bv    = (const float*)d_in[15];
    const float* wp    = (const float*)d_in[16];
    const float* bp    = (const float*)d_in[17];
    float* out = (float*)d_out;

    const int SMEM = 96 * 1024;
    cudaFuncSetAttribute(ln_proj_kernel,  cudaFuncAttributeMaxDynamicSharedMemorySize, SMEM);
    cudaFuncSetAttribute(attn_kernel,     cudaFuncAttributeMaxDynamicSharedMemorySize, SMEM);
    cudaFuncSetAttribute(out_proj_kernel, cudaFuncAttributeMaxDynamicSharedMemorySize, SMEM);

    ln_proj_kernel<<<dim3(TOKENS / 64, 3), 256, SMEM>>>(
        q, k, v, lnq_g, lnq_b, lnk_g, lnk_b, lnv_g, lnv_b,
        wq, bq, wk, bk, wv, bv);

    attn_kernel<<<NBL * HEADS, 384, SMEM>>>();

    out_proj_kernel<<<R2ROWS / 64, 256, SMEM>>>(wp, bp, skip, out);
}

// round 2
// speedup vs baseline: 1.9099x; 1.9099x over previous
#include <cuda_runtime.h>
#include <cstdint>

// Problem constants
#define BATCH   2
#define NVIEW   6
#define XD      8
#define YD      8
#define W1D     8
#define W2D     8
#define DIM     128
#define HEADS   4
#define DHEAD   32
#define HDIM    128
#define LWIN    64
#define QTOK    384
#define NBL     128
#define TOKENS  49152
#define R2ROWS  8192
#define EPS     1e-5f
#define FULLMASK 0xffffffffu

// Scratch (device globals; no allocation allowed)
__device__ float g_qp[TOKENS * HDIM];
__device__ float g_kp[TOKENS * HDIM];
__device__ float g_vp[TOKENS * HDIM];
__device__ float g_at[TOKENS * HDIM];

__device__ __forceinline__ float tf32r(float x) {
    float y; asm("cvt.rna.tf32.f32 %0, %1;" : "=f"(y) : "f"(x)); return y;
}
// D += A(16x8) * B(8x8), tf32 inputs, fp32 accum
__device__ __forceinline__ void mma8(float* d, const uint32_t* a, const uint32_t* b) {
    asm volatile("mma.sync.aligned.m16n8k8.row.col.f32.tf32.tf32.f32 "
        "{%0,%1,%2,%3}, {%4,%5,%6,%7}, {%8,%9}, {%0,%1,%2,%3};"
        : "+f"(d[0]), "+f"(d[1]), "+f"(d[2]), "+f"(d[3])
        : "r"(a[0]), "r"(a[1]), "r"(a[2]), "r"(a[3]), "r"(b[0]), "r"(b[1]));
}

// ---------------------------------------------------------------------------
// Kernel 1: fold + LayerNorm + projection GEMM (tf32 mma).
// grid = (384, 3), block = 256 (8 warps). Block tile 128 rows x 128 cols.
// smem: Xs 128x132 + Ws 128x136 (padded strides -> conflict-free frag loads)
// ---------------------------------------------------------------------------
#define XS_STR 132
#define WS_STR 136
#define K1_SMEM ((128*XS_STR + 128*WS_STR) * 4)

__global__ __launch_bounds__(256) void ln_proj_mma(
    const float* __restrict__ q, const float* __restrict__ k, const float* __restrict__ v,
    const float* __restrict__ lnq_g, const float* __restrict__ lnq_b,
    const float* __restrict__ lnk_g, const float* __restrict__ lnk_b,
    const float* __restrict__ lnv_g, const float* __restrict__ lnv_b,
    const float* __restrict__ wq, const float* __restrict__ bq,
    const float* __restrict__ wk, const float* __restrict__ bk,
    const float* __restrict__ wv, const float* __restrict__ bv)
{
    extern __shared__ float sm[];
    float* Xs = sm;                    // 128 x 132
    float* Ws = sm + 128 * XS_STR;     // 128 x 136

    const float* src; const float* gam; const float* bet;
    const float* W; const float* bias; float* dst;
    int mat = blockIdx.y;
    if (mat == 0)      { src = q; gam = lnq_g; bet = lnq_b; W = wq; bias = bq; dst = g_qp; }
    else if (mat == 1) { src = k; gam = lnk_g; bet = lnk_b; W = wk; bias = bk; dst = g_kp; }
    else               { src = v; gam = lnv_g; bet = lnv_b; W = wv; bias = bv; dst = g_vp; }

    int tid  = threadIdx.x;
    int warp = tid >> 5;
    int lane = tid & 31;
    int row0 = blockIdx.x * 128;

    // Load W into padded smem, tf32-rounded
    for (int i = tid; i < 128 * 32; i += 256) {
        int r = i >> 5, c4 = i & 31;
        float4 w4 = ((const float4*)W)[i];
        w4.x = tf32r(w4.x); w4.y = tf32r(w4.y); w4.z = tf32r(w4.z); w4.w = tf32r(w4.w);
        *(float4*)(Ws + r * WS_STR + c4 * 4) = w4;
    }

    // LayerNorm 128 tokens: warp per token, 16 iterations
    float4 gg  = ((const float4*)gam)[lane];
    float4 bb4 = ((const float4*)bet)[lane];
    for (int it = 0; it < 16; ++it) {
        int rloc = it * 8 + warp;
        int r = row0 + rloc;
        int bIdx = r / (LWIN * QTOK);
        int rem  = r % (LWIN * QTOK);
        int l = rem / QTOK;
        int t = rem % QTOK;
        int x = l >> 3, y = l & 7;
        int n = t / 64; int w12 = t & 63; int w1 = w12 >> 3, w2 = w12 & 7;
        int srcOff = (((((bIdx * NVIEW + n) * XD + x) * YD + y) * W1D + w1) * W2D + w2) * DIM;

        float4 xv = ((const float4*)(src + srcOff))[lane];
        float s  = xv.x + xv.y + xv.z + xv.w;
        float ss = xv.x * xv.x + xv.y * xv.y + xv.z * xv.z + xv.w * xv.w;
        #pragma unroll
        for (int o = 16; o; o >>= 1) {
            s  += __shfl_xor_sync(FULLMASK, s,  o);
            ss += __shfl_xor_sync(FULLMASK, ss, o);
        }
        float mu  = s * (1.0f / 128.0f);
        float var = ss * (1.0f / 128.0f) - mu * mu;
        float rs  = rsqrtf(var + EPS);
        float4 ov;
        ov.x = tf32r((xv.x - mu) * rs * gg.x + bb4.x);
        ov.y = tf32r((xv.y - mu) * rs * gg.y + bb4.y);
        ov.z = tf32r((xv.z - mu) * rs * gg.z + bb4.z);
        ov.w = tf32r((xv.w - mu) * rs * gg.w + bb4.w);
        *(float4*)(Xs + rloc * XS_STR + lane * 4) = ov;
    }
    __syncthreads();

    // Warp tile: 32 rows x 64 cols. mg = warp>>1 (4 row groups), ng = warp&1
    int mg = warp >> 1, ng = warp & 1;
    int g  = lane >> 2, c = lane & 3;

    float acc[2][8][4];
    #pragma unroll
    for (int mt = 0; mt < 2; ++mt)
        #pragma unroll
        for (int nt = 0; nt < 8; ++nt)
            { acc[mt][nt][0]=0.f; acc[mt][nt][1]=0.f; acc[mt][nt][2]=0.f; acc[mt][nt][3]=0.f; }

    #pragma unroll 4
    for (int kst = 0; kst < 16; ++kst) {
        int k0 = kst * 8;
        uint32_t a[2][4];
        #pragma unroll
        for (int mt = 0; mt < 2; ++mt) {
            const float* ap = Xs + (mg * 32 + mt * 16) * XS_STR + k0;
            a[mt][0] = __float_as_uint(ap[ g      * XS_STR + c    ]);
            a[mt][1] = __float_as_uint(ap[(g + 8) * XS_STR + c    ]);
            a[mt][2] = __float_as_uint(ap[ g      * XS_STR + c + 4]);
            a[mt][3] = __float_as_uint(ap[(g + 8) * XS_STR + c + 4]);
        }
        #pragma unroll
        for (int nt = 0; nt < 8; ++nt) {
            const float* bp_ = Ws + k0 * WS_STR + ng * 64 + nt * 8;
            uint32_t b[2];
            b[0] = __float_as_uint(bp_[ c      * WS_STR + g]);
            b[1] = __float_as_uint(bp_[(c + 4) * WS_STR + g]);
            mma8(acc[0][nt], a[0], b);
            mma8(acc[1][nt], a[1], b);
        }
    }

    // Epilogue: + bias, store
    #pragma unroll
    for (int nt = 0; nt < 8; ++nt) {
        int col = ng * 64 + nt * 8 + c * 2;
        float2 bv2 = *(const float2*)(bias + col);
        #pragma unroll
        for (int mt = 0; mt < 2; ++mt) {
            int rr = row0 + mg * 32 + mt * 16 + g;
            float2 o0 = { acc[mt][nt][0] + bv2.x, acc[mt][nt][1] + bv2.y };
            float2 o1 = { acc[mt][nt][2] + bv2.x, acc[mt][nt][3] + bv2.y };
            *(float2*)(dst + (size_t)rr * 128 + col)       = o0;
            *(float2*)(dst + (size_t)(rr + 8) * 128 + col) = o1;
        }
    }
}

// ---------------------------------------------------------------------------
// Kernel 2: flash attention per (b,l,head), tf32 mma.
// grid = 512, block = 384 (12 warps, each owns 32 q rows = 2 m-tiles).
// smem: Qs 384x36 + Ks 384x36 + Vs 384x40 (padded, conflict-free frag LDS)
// ---------------------------------------------------------------------------
#define QS_STR 36
#define KS_STR 36
#define VS_STR 40
#define K2_SMEM (384 * (QS_STR + KS_STR + VS_STR) * 4)

__global__ __launch_bounds__(384) void attn_mma()
{
    extern __shared__ float sm[];
    float* Qs  = sm;                       // 384 x 36
    float* Ksm = Qs  + 384 * QS_STR;       // 384 x 36
    float* Vsm = Ksm + 384 * KS_STR;       // 384 x 40

    int bl = blockIdx.x >> 2;
    int m  = blockIdx.x & 3;
    size_t base = (size_t)bl * QTOK * 128 + m * 32;

    int tid = threadIdx.x, warp = tid >> 5, lane = tid & 31;
    int g = lane >> 2, c = lane & 3;

    // scale * log2(e): softmax done in exp2 domain
    const float qscale = 0.1767766952966369f * 1.4426950408889634f;

    // Load Q (pre-scaled), K, V head slices into padded smem, tf32-rounded
    for (int i = tid; i < QTOK * 8; i += 384) {
        int row = i >> 3, c4 = i & 7;
        float4 t;
        t = ((const float4*)(g_qp + base + (size_t)row * 128))[c4];
        t.x = tf32r(t.x * qscale); t.y = tf32r(t.y * qscale);
        t.z = tf32r(t.z * qscale); t.w = tf32r(t.w * qscale);
        *(float4*)(Qs + row * QS_STR + c4 * 4) = t;
        t = ((const float4*)(g_kp + base + (size_t)row * 128))[c4];
        t.x = tf32r(t.x); t.y = tf32r(t.y); t.z = tf32r(t.z); t.w = tf32r(t.w);
        *(float4*)(Ksm + row * KS_STR + c4 * 4) = t;
        t = ((const float4*)(g_vp + base + (size_t)row * 128))[c4];
        t.x = tf32r(t.x); t.y = tf32r(t.y); t.z = tf32r(t.z); t.w = tf32r(t.w);
        *(float4*)(Vsm + row * VS_STR + c4 * 4) = t;
    }
    __syncthreads();

    // Q fragments, loaded once: [mt][kst][reg]
    int q0 = warp * 32;
    uint32_t qa[2][4][4];
    #pragma unroll
    for (int mt = 0; mt < 2; ++mt)
        #pragma unroll
        for (int kst = 0; kst < 4; ++kst) {
            const float* ap = Qs + (q0 + mt * 16) * QS_STR + kst * 8;
            qa[mt][kst][0] = __float_as_uint(ap[ g      * QS_STR + c    ]);
            qa[mt][kst][1] = __float_as_uint(ap[(g + 8) * QS_STR + c    ]);
            qa[mt][kst][2] = __float_as_uint(ap[ g      * QS_STR + c + 4]);
            qa[mt][kst][3] = __float_as_uint(ap[(g + 8) * QS_STR + c + 4]);
        }

    float o[2][4][4];
    #pragma unroll
    for (int mt = 0; mt < 2; ++mt)
        #pragma unroll
        for (int nt = 0; nt < 4; ++nt)
            { o[mt][nt][0]=0.f; o[mt][nt][1]=0.f; o[mt][nt][2]=0.f; o[mt][nt][3]=0.f; }
    float mrun[2][2] = {{-1e30f,-1e30f},{-1e30f,-1e30f}};
    float lrun[2][2] = {{0.f,0.f},{0.f,0.f}};

    int qb   = lane & ~3;
    int srcA = qb + (c >> 1);
    int srcB = srcA + 2;

    for (int kc = 0; kc < QTOK; kc += 32) {
        // S = Q K^T for 32 keys: [mt][nt(keytile)][reg]
        float s[2][4][4];
        #pragma unroll
        for (int mt = 0; mt < 2; ++mt)
            #pragma unroll
            for (int nt = 0; nt < 4; ++nt)
                { s[mt][nt][0]=0.f; s[mt][nt][1]=0.f; s[mt][nt][2]=0.f; s[mt][nt][3]=0.f; }

        #pragma unroll
        for (int kst = 0; kst < 4; ++kst) {
            #pragma unroll
            for (int nt = 0; nt < 4; ++nt) {
                const float* bp_ = Ksm + (kc + nt * 8) * KS_STR + kst * 8;
                uint32_t b[2];
                b[0] = __float_as_uint(bp_[g * KS_STR + c    ]);
                b[1] = __float_as_uint(bp_[g * KS_STR + c + 4]);
                mma8(s[0][nt], qa[0][kst], b);
                mma8(s[1][nt], qa[1][kst], b);
            }
        }

        // Online softmax (exp2 domain)
        #pragma unroll
        for (int mt = 0; mt < 2; ++mt) {
            float cm0 = s[mt][0][0], cm1 = s[mt][0][2];
            #pragma unroll
            for (int nt = 0; nt < 4; ++nt) {
                cm0 = fmaxf(cm0, fmaxf(s[mt][nt][0], s[mt][nt][1]));
                cm1 = fmaxf(cm1, fmaxf(s[mt][nt][2], s[mt][nt][3]));
            }
            cm0 = fmaxf(cm0, __shfl_xor_sync(FULLMASK, cm0, 1));
            cm0 = fmaxf(cm0, __shfl_xor_sync(FULLMASK, cm0, 2));
            cm1 = fmaxf(cm1, __shfl_xor_sync(FULLMASK, cm1, 1));
            cm1 = fmaxf(cm1, __shfl_xor_sync(FULLMASK, cm1, 2));
            float mn0 = fmaxf(mrun[mt][0], cm0);
            float mn1 = fmaxf(mrun[mt][1], cm1);
            float f0 = exp2f(mrun[mt][0] - mn0);
            float f1 = exp2f(mrun[mt][1] - mn1);
            float rs0 = 0.f, rs1 = 0.f;
            #pragma unroll
            for (int nt = 0; nt < 4; ++nt) {
                s[mt][nt][0] = exp2f(s[mt][nt][0] - mn0);
                s[mt][nt][1] = exp2f(s[mt][nt][1] - mn0);
                s[mt][nt][2] = exp2f(s[mt][nt][2] - mn1);
                s[mt][nt][3] = exp2f(s[mt][nt][3] - mn1);
                rs0 += s[mt][nt][0] + s[mt][nt][1];
                rs1 += s[mt][nt][2] + s[mt][nt][3];
            }
            rs0 += __shfl_xor_sync(FULLMASK, rs0, 1);
            rs0 += __shfl_xor_sync(FULLMASK, rs0, 2);
            rs1 += __shfl_xor_sync(FULLMASK, rs1, 1);
            rs1 += __shfl_xor_sync(FULLMASK, rs1, 2);
            lrun[mt][0] = lrun[mt][0] * f0 + rs0;
            lrun[mt][1] = lrun[mt][1] * f1 + rs1;
            mrun[mt][0] = mn0; mrun[mt][1] = mn1;
            #pragma unroll
            for (int nt = 0; nt < 4; ++nt) {
                o[mt][nt][0] *= f0; o[mt][nt][1] *= f0;
                o[mt][nt][2] *= f1; o[mt][nt][3] *= f1;
            }
        }

        // Repack P (D-frag -> A-frag via intra-quad shfl), then O += P V
        #pragma unroll
        for (int kt = 0; kt < 4; ++kt) {
            uint32_t pa[2][4];
            #pragma unroll
            for (int mt = 0; mt < 2; ++mt) {
                float e0 = s[mt][kt][0], e1 = s[mt][kt][1];
                float e2 = s[mt][kt][2], e3 = s[mt][kt][3];
                float tA0 = __shfl_sync(FULLMASK, e0, srcA);
                float tA1 = __shfl_sync(FULLMASK, e1, srcA);
                float tB0 = __shfl_sync(FULLMASK, e0, srcB);
                float tB1 = __shfl_sync(FULLMASK, e1, srcB);
                float tA2 = __shfl_sync(FULLMASK, e2, srcA);
                float tA3 = __shfl_sync(FULLMASK, e3, srcA);
                float tB2 = __shfl_sync(FULLMASK, e2, srcB);
                float tB3 = __shfl_sync(FULLMASK, e3, srcB);
                float a0 = (c & 1) ? tA1 : tA0;   // row g,   col c
                float a2 = (c & 1) ? tB1 : tB0;   // row g,   col c+4
                float a1 = (c & 1) ? tA3 : tA2;   // row g+8, col c
                float a3 = (c & 1) ? tB3 : tB2;   // row g+8, col c+4
                pa[mt][0] = __float_as_uint(tf32r(a0));
                pa[mt][1] = __float_as_uint(tf32r(a1));
                pa[mt][2] = __float_as_uint(tf32r(a2));
                pa[mt][3] = __float_as_uint(tf32r(a3));
            }
            #pragma unroll
            for (int nt = 0; nt < 4; ++nt) {
                const float* vp_ = Vsm + (kc + kt * 8) * VS_STR + nt * 8;
                uint32_t vb[2];
                vb[0] = __float_as_uint(vp_[ c      * VS_STR + g]);
                vb[1] = __float_as_uint(vp_[(c + 4) * VS_STR + g]);
                mma8(o[0][nt], pa[0], vb);
                mma8(o[1][nt], pa[1], vb);
            }
        }
    }

    // Finalize: divide by l, store
    #pragma unroll
    for (int mt = 0; mt < 2; ++mt) {
        float inv0 = 1.0f / lrun[mt][0];
        float inv1 = 1.0f / lrun[mt][1];
        int r0 = q0 + mt * 16 + g;
        #pragma unroll
        for (int nt = 0; nt < 4; ++nt) {
            int col = nt * 8 + c * 2;
            float2 v0 = { o[mt][nt][0] * inv0, o[mt][nt][1] * inv0 };
            float2 v1 = { o[mt][nt][2] * inv1, o[mt][nt][3] * inv1 };
            *(float2*)(g_at + base + (size_t)r0 * 128 + col)       = v0;
            *(float2*)(g_at + base + (size_t)(r0 + 8) * 128 + col) = v1;
        }
    }
}

// ---------------------------------------------------------------------------
// Kernel 3: fused mean-over-views + output projection + bias + skip (fp32).
// ---------------------------------------------------------------------------
__global__ __launch_bounds__(256) void out_proj_kernel(
    const float* __restrict__ wp, const float* __restrict__ bp,
    const float* __restrict__ skip, float* __restrict__ out)
{
    extern __shared__ float sm[];
    float* Xs = sm;                 // 64*128
    float* Ws = sm + 64 * 128;      // 128*128

    int tid  = threadIdx.x;
    int row0 = blockIdx.x * 64;

    for (int i = tid; i < 128 * 32; i += 256)
        ((float4*)Ws)[i] = ((const float4*)wp)[i];

    for (int i = tid; i < 64 * 32; i += 256) {
        int rloc = i >> 5, c = i & 31;
        int r2 = row0 + rloc;
        int bl = r2 >> 6;
        int w  = r2 & 63;
        float4 a; a.x = 0.f; a.y = 0.f; a.z = 0.f; a.w = 0.f;
        #pragma unroll
        for (int n = 0; n < NVIEW; ++n) {
            float4 t = ((const float4*)(g_at + ((size_t)(bl * QTOK + n * 64 + w)) * 128))[c];
            a.x += t.x; a.y += t.y; a.z += t.z; a.w += t.w;
        }
        const float invn = 1.0f / 6.0f;
        a.x *= invn; a.y *= invn; a.z *= invn; a.w *= invn;
        ((float4*)Xs)[rloc * 32 + c] = a;
    }
    __syncthreads();

    int ti = tid >> 5;
    int cj = tid & 31;
    float acc[8][4];
    #pragma unroll
    for (int i = 0; i < 8; ++i) { acc[i][0]=0.f; acc[i][1]=0.f; acc[i][2]=0.f; acc[i][3]=0.f; }

    const float4* Ws4 = (const float4*)Ws;
    #pragma unroll 8
    for (int kk = 0; kk < 128; ++kk) {
        float4 wv = Ws4[kk * 32 + cj];
        #pragma unroll
        for (int i = 0; i < 8; ++i) {
            float xv = Xs[(ti * 8 + i) * 128 + kk];
            acc[i][0] += xv * wv.x;
            acc[i][1] += xv * wv.y;
            acc[i][2] += xv * wv.z;
            acc[i][3] += xv * wv.w;
        }
    }

    float4 bsv = ((const float4*)bp)[cj];
    #pragma unroll
    for (int i = 0; i < 8; ++i) {
        int r = row0 + ti * 8 + i;
        float4 sk = ((const float4*)(skip + (size_t)r * 128))[cj];
        float4 o;
        o.x = acc[i][0] + bsv.x + sk.x;
        o.y = acc[i][1] + bsv.y + sk.y;
        o.z = acc[i][2] + bsv.z + sk.z;
        o.w = acc[i][3] + bsv.w + sk.w;
        ((float4*)(out + (size_t)r * 128))[cj] = o;
    }
}

// ---------------------------------------------------------------------------
extern "C" void kernel_launch(void* const* d_in, const int* in_sizes, int n_in,
                              void* d_out, int out_size)
{
    const float* q     = (const float*)d_in[0];
    const float* k     = (const float*)d_in[1];
    const float* v     = (const float*)d_in[2];
    const float* skip  = (const float*)d_in[3];
    const float* lnq_g = (const float*)d_in[4];
    const float* lnq_b = (const float*)d_in[5];
    const float* lnk_g = (const float*)d_in[6];
    const float* lnk_b = (const float*)d_in[7];
    const float* lnv_g = (const float*)d_in[8];
    const float* lnv_b = (const float*)d_in[9];
    const float* wq    = (const float*)d_in[10];
    const float* bq    = (const float*)d_in[11];
    const float* wk    = (const float*)d_in[12];
    const float* bk    = (const float*)d_in[13];
    const float* wv    = (const float*)d_in[14];
    const float* bv    = (const float*)d_in[15];
    const float* wp    = (const float*)d_in[16];
    const float* bp    = (const float*)d_in[17];
    float* out = (float*)d_out;

    cudaFuncSetAttribute(ln_proj_mma,    cudaFuncAttributeMaxDynamicSharedMemorySize, K1_SMEM);
    cudaFuncSetAttribute(attn_mma,       cudaFuncAttributeMaxDynamicSharedMemorySize, K2_SMEM);
    cudaFuncSetAttribute(out_proj_kernel, cudaFuncAttributeMaxDynamicSharedMemorySize, 96 * 1024);

    ln_proj_mma<<<dim3(TOKENS / 128, 3), 256, K1_SMEM>>>(
        q, k, v, lnq_g, lnq_b, lnk_g, lnk_b, lnv_g, lnv_b,
        wq, bq, wk, bk, wv, bv);

    attn_mma<<<NBL * HEADS, 384, K2_SMEM>>>();

    out_proj_kernel<<<R2ROWS / 64, 256, 96 * 1024>>>(wp, bp, skip, out);
}

// round 3
// speedup vs baseline: 2.7217x; 1.4250x over previous
#include <cuda_runtime.h>
#include <cstdint>

// Problem constants
#define BATCH   2
#define NVIEW   6
#define XD      8
#define YD      8
#define W1D     8
#define W2D     8
#define DIM     128
#define HEADS   4
#define DHEAD   32
#define HDIM    128
#define LWIN    64
#define QTOK    384
#define NBL     128
#define TOKENS  49152
#define R2ROWS  8192
#define EPS     1e-5f
#define FULLMASK 0xffffffffu

// Scratch (device globals; no allocation allowed)
__device__ float g_qp[TOKENS * HDIM];
__device__ float g_kp[TOKENS * HDIM];
__device__ float g_vp[TOKENS * HDIM];
__device__ float g_at[TOKENS * HDIM];

__device__ __forceinline__ float tf32r(float x) {
    float y; asm("cvt.rna.tf32.f32 %0, %1;" : "=f"(y) : "f"(x)); return y;
}
// D += A(16x8) * B(8x8), tf32 inputs, fp32 accum
__device__ __forceinline__ void mma8(float* d, const uint32_t* a, const uint32_t* b) {
    asm volatile("mma.sync.aligned.m16n8k8.row.col.f32.tf32.tf32.f32 "
        "{%0,%1,%2,%3}, {%4,%5,%6,%7}, {%8,%9}, {%0,%1,%2,%3};"
        : "+f"(d[0]), "+f"(d[1]), "+f"(d[2]), "+f"(d[3])
        : "r"(a[0]), "r"(a[1]), "r"(a[2]), "r"(a[3]), "r"(b[0]), "r"(b[1]));
}

// ---------------------------------------------------------------------------
// Kernel 1: fold + LayerNorm + projection GEMM (tf32 mma).
// grid = (768, 3), block = 256 (8 warps). Block tile 64 rows x 128 cols.
// smem: Xs 64x132 + Ws 128x136 = 103 KB -> 2 CTAs/SM.
// Warp tile 32 rows x 32 cols: mg = warp>>2, ng = warp&3.
// ---------------------------------------------------------------------------
#define XS_STR 132
#define WS_STR 136
#define K1_SMEM ((64*XS_STR + 128*WS_STR) * 4)

__global__ __launch_bounds__(256, 2) void ln_proj_mma(
    const float* __restrict__ q, const float* __restrict__ k, const float* __restrict__ v,
    const float* __restrict__ lnq_g, const float* __restrict__ lnq_b,
    const float* __restrict__ lnk_g, const float* __restrict__ lnk_b,
    const float* __restrict__ lnv_g, const float* __restrict__ lnv_b,
    const float* __restrict__ wq, const float* __restrict__ bq,
    const float* __restrict__ wk, const float* __restrict__ bk,
    const float* __restrict__ wv, const float* __restrict__ bv)
{
    extern __shared__ float sm[];
    float* Xs = sm;                    // 64 x 132
    float* Ws = sm + 64 * XS_STR;      // 128 x 136

    const float* src; const float* gam; const float* bet;
    const float* W; const float* bias; float* dst;
    int mat = blockIdx.y;
    if (mat == 0)      { src = q; gam = lnq_g; bet = lnq_b; W = wq; bias = bq; dst = g_qp; }
    else if (mat == 1) { src = k; gam = lnk_g; bet = lnk_b; W = wk; bias = bk; dst = g_kp; }
    else               { src = v; gam = lnv_g; bet = lnv_b; W = wv; bias = bv; dst = g_vp; }

    int tid  = threadIdx.x;
    int warp = tid >> 5;
    int lane = tid & 31;
    int row0 = blockIdx.x * 64;

    // Load W into padded smem, tf32-rounded
    for (int i = tid; i < 128 * 32; i += 256) {
        int r = i >> 5, c4 = i & 31;
        float4 w4 = ((const float4*)W)[i];
        w4.x = tf32r(w4.x); w4.y = tf32r(w4.y); w4.z = tf32r(w4.z); w4.w = tf32r(w4.w);
        *(float4*)(Ws + r * WS_STR + c4 * 4) = w4;
    }

    // LayerNorm 64 tokens: warp per token, 8 iterations
    float4 gg  = ((const float4*)gam)[lane];
    float4 bb4 = ((const float4*)bet)[lane];
    #pragma unroll
    for (int it = 0; it < 8; ++it) {
        int rloc = it * 8 + warp;
        int r = row0 + rloc;
        int bIdx = r / (LWIN * QTOK);
        int rem  = r % (LWIN * QTOK);
        int l = rem / QTOK;
        int t = rem % QTOK;
        int x = l >> 3, y = l & 7;
        int n = t / 64; int w12 = t & 63; int w1 = w12 >> 3, w2 = w12 & 7;
        int srcOff = (((((bIdx * NVIEW + n) * XD + x) * YD + y) * W1D + w1) * W2D + w2) * DIM;

        float4 xv = ((const float4*)(src + srcOff))[lane];
        float s  = xv.x + xv.y + xv.z + xv.w;
        float ss = xv.x * xv.x + xv.y * xv.y + xv.z * xv.z + xv.w * xv.w;
        #pragma unroll
        for (int o = 16; o; o >>= 1) {
            s  += __shfl_xor_sync(FULLMASK, s,  o);
            ss += __shfl_xor_sync(FULLMASK, ss, o);
        }
        float mu  = s * (1.0f / 128.0f);
        float var = ss * (1.0f / 128.0f) - mu * mu;
        float rs  = rsqrtf(var + EPS);
        float4 ov;
        ov.x = tf32r((xv.x - mu) * rs * gg.x + bb4.x);
        ov.y = tf32r((xv.y - mu) * rs * gg.y + bb4.y);
        ov.z = tf32r((xv.z - mu) * rs * gg.z + bb4.z);
        ov.w = tf32r((xv.w - mu) * rs * gg.w + bb4.w);
        *(float4*)(Xs + rloc * XS_STR + lane * 4) = ov;
    }
    __syncthreads();

    // Warp tile: 32 rows x 32 cols. mg = warp>>2, ng = warp&3
    int mg = warp >> 2, ng = warp & 3;
    int g  = lane >> 2, c = lane & 3;

    float acc[2][4][4];
    #pragma unroll
    for (int mt = 0; mt < 2; ++mt)
        #pragma unroll
        for (int nt = 0; nt < 4; ++nt)
            { acc[mt][nt][0]=0.f; acc[mt][nt][1]=0.f; acc[mt][nt][2]=0.f; acc[mt][nt][3]=0.f; }

    #pragma unroll 4
    for (int kst = 0; kst < 16; ++kst) {
        int k0 = kst * 8;
        uint32_t a[2][4];
        #pragma unroll
        for (int mt = 0; mt < 2; ++mt) {
            const float* ap = Xs + (mg * 32 + mt * 16) * XS_STR + k0;
            a[mt][0] = __float_as_uint(ap[ g      * XS_STR + c    ]);
            a[mt][1] = __float_as_uint(ap[(g + 8) * XS_STR + c    ]);
            a[mt][2] = __float_as_uint(ap[ g      * XS_STR + c + 4]);
            a[mt][3] = __float_as_uint(ap[(g + 8) * XS_STR + c + 4]);
        }
        #pragma unroll
        for (int nt = 0; nt < 4; ++nt) {
            const float* bp_ = Ws + k0 * WS_STR + ng * 32 + nt * 8;
            uint32_t b[2];
            b[0] = __float_as_uint(bp_[ c      * WS_STR + g]);
            b[1] = __float_as_uint(bp_[(c + 4) * WS_STR + g]);
            mma8(acc[0][nt], a[0], b);
            mma8(acc[1][nt], a[1], b);
        }
    }

    // Epilogue: + bias, store
    #pragma unroll
    for (int nt = 0; nt < 4; ++nt) {
        int col = ng * 32 + nt * 8 + c * 2;
        float2 bv2 = *(const float2*)(bias + col);
        #pragma unroll
        for (int mt = 0; mt < 2; ++mt) {
            int rr = row0 + mg * 32 + mt * 16 + g;
            float2 o0 = { acc[mt][nt][0] + bv2.x, acc[mt][nt][1] + bv2.y };
            float2 o1 = { acc[mt][nt][2] + bv2.x, acc[mt][nt][3] + bv2.y };
            *(float2*)(dst + (size_t)rr * 128 + col)       = o0;
            *(float2*)(dst + (size_t)(rr + 8) * 128 + col) = o1;
        }
    }
}

// ---------------------------------------------------------------------------
// Kernel 2: flash attention, tf32 mma. 2 blocks per (b,l,head), each block
// covers 192 q rows (12 warps x 16 rows). grid = 1024, block = 384.
// smem: Ks 384x32 (XOR-swizzled) + Vs 384x40 (padded) = 108 KB -> 2 CTAs/SM.
// Q fragments loaded directly from gmem.
// ---------------------------------------------------------------------------
#define VS_STR 40
#define K2_SMEM ((QTOK*32 + QTOK*VS_STR) * 4)

__global__ __launch_bounds__(384, 2) void attn_mma()
{
    extern __shared__ float sm[];
    float* Ksm = sm;               // 384 x 32, xor-swizzled
    float* Vsm = sm + QTOK * 32;   // 384 x 40

    int bx   = blockIdx.x;
    int bl   = bx >> 3;
    int m    = (bx >> 1) & 3;
    int half = bx & 1;
    size_t base = (size_t)bl * QTOK * 128 + m * 32;

    int tid = threadIdx.x, warp = tid >> 5, lane = tid & 31;
    int g = lane >> 2, c = lane & 3;
    int swz = g << 2;

    const float qscale = 0.1767766952966369f * 1.4426950408889634f;

    // Fill K (swizzled) and V (padded) for the whole window
    for (int i = tid; i < QTOK * 8; i += 384) {
        int row = i >> 3, c4 = i & 7;
        float4 t;
        t = ((const float4*)(g_kp + base + (size_t)row * 128))[c4];
        t.x = tf32r(t.x); t.y = tf32r(t.y); t.z = tf32r(t.z); t.w = tf32r(t.w);
        *(float4*)(Ksm + row * 32 + ((c4 * 4) ^ ((row & 7) << 2))) = t;
        t = ((const float4*)(g_vp + base + (size_t)row * 128))[c4];
        t.x = tf32r(t.x); t.y = tf32r(t.y); t.z = tf32r(t.z); t.w = tf32r(t.w);
        *(float4*)(Vsm + row * VS_STR + c4 * 4) = t;
    }

    // Q fragments straight from gmem (16 rows per warp), pre-scaled
    int q0 = half * 192 + warp * 16;
    uint32_t qa[4][4];
    {
        const float* qr0 = g_qp + base + (size_t)(q0 + g) * 128;
        const float* qr1 = g_qp + base + (size_t)(q0 + g + 8) * 128;
        #pragma unroll
        for (int kst = 0; kst < 4; ++kst) {
            qa[kst][0] = __float_as_uint(tf32r(qr0[kst * 8 + c    ] * qscale));
            qa[kst][1] = __float_as_uint(tf32r(qr1[kst * 8 + c    ] * qscale));
            qa[kst][2] = __float_as_uint(tf32r(qr0[kst * 8 + c + 4] * qscale));
            qa[kst][3] = __float_as_uint(tf32r(qr1[kst * 8 + c + 4] * qscale));
        }
    }
    __syncthreads();

    float o[4][4];
    #pragma unroll
    for (int nt = 0; nt < 4; ++nt)
        { o[nt][0]=0.f; o[nt][1]=0.f; o[nt][2]=0.f; o[nt][3]=0.f; }
    float mrun0 = -1e30f, mrun1 = -1e30f;
    float lrun0 = 0.f, lrun1 = 0.f;

    int qb   = lane & ~3;
    int srcA = qb + (c >> 1);
    int srcB = srcA + 2;

    for (int kc = 0; kc < QTOK; kc += 32) {
        // S = Q K^T for 32 keys
        float s[4][4];
        #pragma unroll
        for (int nt = 0; nt < 4; ++nt)
            { s[nt][0]=0.f; s[nt][1]=0.f; s[nt][2]=0.f; s[nt][3]=0.f; }

        #pragma unroll
        for (int kst = 0; kst < 4; ++kst) {
            #pragma unroll
            for (int nt = 0; nt < 4; ++nt) {
                const float* krow = Ksm + (kc + nt * 8 + g) * 32;
                uint32_t b[2];
                b[0] = __float_as_uint(krow[(kst * 8 + c    ) ^ swz]);
                b[1] = __float_as_uint(krow[(kst * 8 + c + 4) ^ swz]);
                mma8(s[nt], qa[kst], b);
            }
        }

        // Online softmax (exp2 domain)
        float cm0 = s[0][0], cm1 = s[0][2];
        #pragma unroll
        for (int nt = 0; nt < 4; ++nt) {
            cm0 = fmaxf(cm0, fmaxf(s[nt][0], s[nt][1]));
            cm1 = fmaxf(cm1, fmaxf(s[nt][2], s[nt][3]));
        }
        cm0 = fmaxf(cm0, __shfl_xor_sync(FULLMASK, cm0, 1));
        cm0 = fmaxf(cm0, __shfl_xor_sync(FULLMASK, cm0, 2));
        cm1 = fmaxf(cm1, __shfl_xor_sync(FULLMASK, cm1, 1));
        cm1 = fmaxf(cm1, __shfl_xor_sync(FULLMASK, cm1, 2));
        float mn0 = fmaxf(mrun0, cm0);
        float mn1 = fmaxf(mrun1, cm1);
        float f0 = exp2f(mrun0 - mn0);
        float f1 = exp2f(mrun1 - mn1);
        float rs0 = 0.f, rs1 = 0.f;
        #pragma unroll
        for (int nt = 0; nt < 4; ++nt) {
            s[nt][0] = exp2f(s[nt][0] - mn0);
            s[nt][1] = exp2f(s[nt][1] - mn0);
            s[nt][2] = exp2f(s[nt][2] - mn1);
            s[nt][3] = exp2f(s[nt][3] - mn1);
            rs0 += s[nt][0] + s[nt][1];
            rs1 += s[nt][2] + s[nt][3];
        }
        rs0 += __shfl_xor_sync(FULLMASK, rs0, 1);
        rs0 += __shfl_xor_sync(FULLMASK, rs0, 2);
        rs1 += __shfl_xor_sync(FULLMASK, rs1, 1);
        rs1 += __shfl_xor_sync(FULLMASK, rs1, 2);
        lrun0 = lrun0 * f0 + rs0;
        lrun1 = lrun1 * f1 + rs1;
        mrun0 = mn0; mrun1 = mn1;
        #pragma unroll
        for (int nt = 0; nt < 4; ++nt) {
            o[nt][0] *= f0; o[nt][1] *= f0;
            o[nt][2] *= f1; o[nt][3] *= f1;
        }

        // Repack P (D-frag -> A-frag via intra-quad shfl), then O += P V
        #pragma unroll
        for (int kt = 0; kt < 4; ++kt) {
            float e0 = s[kt][0], e1 = s[kt][1];
            float e2 = s[kt][2], e3 = s[kt][3];
            float tA0 = __shfl_sync(FULLMASK, e0, srcA);
            float tA1 = __shfl_sync(FULLMASK, e1, srcA);
            float tB0 = __shfl_sync(FULLMASK, e0, srcB);
            float tB1 = __shfl_sync(FULLMASK, e1, srcB);
            float tA2 = __shfl_sync(FULLMASK, e2, srcA);
            float tA3 = __shfl_sync(FULLMASK, e3, srcA);
            float tB2 = __shfl_sync(FULLMASK, e2, srcB);
            float tB3 = __shfl_sync(FULLMASK, e3, srcB);
            float a0 = (c & 1) ? tA1 : tA0;   // row g,   col c
            float a2 = (c & 1) ? tB1 : tB0;   // row g,   col c+4
            float a1 = (c & 1) ? tA3 : tA2;   // row g+8, col c
            float a3 = (c & 1) ? tB3 : tB2;   // row g+8, col c+4
            uint32_t pa[4];
            pa[0] = __float_as_uint(tf32r(a0));
            pa[1] = __float_as_uint(tf32r(a1));
            pa[2] = __float_as_uint(tf32r(a2));
            pa[3] = __float_as_uint(tf32r(a3));
            #pragma unroll
            for (int nt = 0; nt < 4; ++nt) {
                const float* vp_ = Vsm + (kc + kt * 8) * VS_STR + nt * 8;
                uint32_t vb[2];
                vb[0] = __float_as_uint(vp_[ c      * VS_STR + g]);
                vb[1] = __float_as_uint(vp_[(c + 4) * VS_STR + g]);
                mma8(o[nt], pa, vb);
            }
        }
    }

    // Finalize: divide by l, store
    float inv0 = 1.0f / lrun0;
    float inv1 = 1.0f / lrun1;
    int r0 = q0 + g;
    #pragma unroll
    for (int nt = 0; nt < 4; ++nt) {
        int col = nt * 8 + c * 2;
        float2 v0 = { o[nt][0] * inv0, o[nt][1] * inv0 };
        float2 v1 = { o[nt][2] * inv1, o[nt][3] * inv1 };
        *(float2*)(g_at + base + (size_t)r0 * 128 + col)       = v0;
        *(float2*)(g_at + base + (size_t)(r0 + 8) * 128 + col) = v1;
    }
}

// ---------------------------------------------------------------------------
// Kernel 3: fused mean-over-views + output projection + bias + skip (fp32).
// ---------------------------------------------------------------------------
__global__ __launch_bounds__(256) void out_proj_kernel(
    const float* __restrict__ wp, const float* __restrict__ bp,
    const float* __restrict__ skip, float* __restrict__ out)
{
    extern __shared__ float sm[];
    float* Xs = sm;                 // 64*128
    float* Ws = sm + 64 * 128;      // 128*128

    int tid  = threadIdx.x;
    int row0 = blockIdx.x * 64;

    for (int i = tid; i < 128 * 32; i += 256)
        ((float4*)Ws)[i] = ((const float4*)wp)[i];

    for (int i = tid; i < 64 * 32; i += 256) {
        int rloc = i >> 5, c = i & 31;
        int r2 = row0 + rloc;
        int bl = r2 >> 6;
        int w  = r2 & 63;
        float4 a; a.x = 0.f; a.y = 0.f; a.z = 0.f; a.w = 0.f;
        #pragma unroll
        for (int n = 0; n < NVIEW; ++n) {
            float4 t = ((const float4*)(g_at + ((size_t)(bl * QTOK + n * 64 + w)) * 128))[c];
            a.x += t.x; a.y += t.y; a.z += t.z; a.w += t.w;
        }
        const float invn = 1.0f / 6.0f;
        a.x *= invn; a.y *= invn; a.z *= invn; a.w *= invn;
        ((float4*)Xs)[rloc * 32 + c] = a;
    }
    __syncthreads();

    int ti = tid >> 5;
    int cj = tid & 31;
    float acc[8][4];
    #pragma unroll
    for (int i = 0; i < 8; ++i) { acc[i][0]=0.f; acc[i][1]=0.f; acc[i][2]=0.f; acc[i][3]=0.f; }

    const float4* Ws4 = (const float4*)Ws;
    #pragma unroll 8
    for (int kk = 0; kk < 128; ++kk) {
        float4 wv = Ws4[kk * 32 + cj];
        #pragma unroll
        for (int i = 0; i < 8; ++i) {
            float xv = Xs[(ti * 8 + i) * 128 + kk];
            acc[i][0] += xv * wv.x;
            acc[i][1] += xv * wv.y;
            acc[i][2] += xv * wv.z;
            acc[i][3] += xv * wv.w;
        }
    }

    float4 bsv = ((const float4*)bp)[cj];
    #pragma unroll
    for (int i = 0; i < 8; ++i) {
        int r = row0 + ti * 8 + i;
        float4 sk = ((const float4*)(skip + (size_t)r * 128))[cj];
        float4 o;
        o.x = acc[i][0] + bsv.x + sk.x;
        o.y = acc[i][1] + bsv.y + sk.y;
        o.z = acc[i][2] + bsv.z + sk.z;
        o.w = acc[i][3] + bsv.w + sk.w;
        ((float4*)(out + (size_t)r * 128))[cj] = o;
    }
}

// ---------------------------------------------------------------------------
extern "C" void kernel_launch(void* const* d_in, const int* in_sizes, int n_in,
                              void* d_out, int out_size)
{
    const float* q     = (const float*)d_in[0];
    const float* k     = (const float*)d_in[1];
    const float* v     = (const float*)d_in[2];
    const float* skip  = (const float*)d_in[3];
    const float* lnq_g = (const float*)d_in[4];
    const float* lnq_b = (const float*)d_in[5];
    const float* lnk_g = (const float*)d_in[6];
    const float* lnk_b = (const float*)d_in[7];
    const float* lnv_g = (const float*)d_in[8];
    const float* lnv_b = (const float*)d_in[9];
    const float* wq    = (const float*)d_in[10];
    const float* bq    = (const float*)d_in[11];
    const float* wk    = (const float*)d_in[12];
    const float* bk    = (const float*)d_in[13];
    const float* wv    = (const float*)d_in[14];
    const float* bv    = (const float*)d_in[15];
    const float* wp    = (const float*)d_in[16];
    const float* bp    = (const float*)d_in[17];
    float* out = (float*)d_out;

    cudaFuncSetAttribute(ln_proj_mma,     cudaFuncAttributeMaxDynamicSharedMemorySize, K1_SMEM);
    cudaFuncSetAttribute(attn_mma,        cudaFuncAttributeMaxDynamicSharedMemorySize, K2_SMEM);
    cudaFuncSetAttribute(out_proj_kernel, cudaFuncAttributeMaxDynamicSharedMemorySize, 96 * 1024);

    ln_proj_mma<<<dim3(TOKENS / 64, 3), 256, K1_SMEM>>>(
        q, k, v, lnq_g, lnq_b, lnk_g, lnk_b, lnv_g, lnv_b,
        wq, bq, wk, bk, wv, bv);

    attn_mma<<<NBL * HEADS * 2, 384, K2_SMEM>>>();

    out_proj_kernel<<<R2ROWS / 64, 256, 96 * 1024>>>(wp, bp, skip, out);
}

// round 4
// speedup vs baseline: 3.9282x; 1.4433x over previous
#include <cuda_runtime.h>
#include <cstdint>

// Problem constants
#define BATCH   2
#define NVIEW   6
#define XD      8
#define YD      8
#define W1D     8
#define W2D     8
#define DIM     128
#define HEADS   4
#define DHEAD   32
#define HDIM    128
#define LWIN    64
#define QTOK    384
#define NBL     128
#define TOKENS  49152
#define R2ROWS  8192
#define EPS     1e-5f
#define FULLMASK 0xffffffffu

// Scratch: bf16 intermediates stored as packed uint32 (2 bf16 per word, 64 words/row)
__device__ uint32_t g_qp[TOKENS * 64];
__device__ uint32_t g_kp[TOKENS * 64];
__device__ uint32_t g_vp[TOKENS * 64];
__device__ uint32_t g_at[TOKENS * 64];

// pack two f32 -> bf16x2 word {lo, hi}
__device__ __forceinline__ uint32_t packbf(float lo, float hi) {
    uint32_t d;
    asm("cvt.rn.bf16x2.f32 %0, %1, %2;" : "=r"(d) : "f"(hi), "f"(lo));
    return d;
}
__device__ __forceinline__ float bflo(uint32_t u) { return __uint_as_float(u << 16); }
__device__ __forceinline__ float bfhi(uint32_t u) { return __uint_as_float(u & 0xffff0000u); }

// D += A(16x16) * B(16x8), bf16 inputs, fp32 accum
__device__ __forceinline__ void mma16(float* d, const uint32_t* a, const uint32_t* b) {
    asm volatile("mma.sync.aligned.m16n8k16.row.col.f32.bf16.bf16.f32 "
        "{%0,%1,%2,%3}, {%4,%5,%6,%7}, {%8,%9}, {%0,%1,%2,%3};"
        : "+f"(d[0]), "+f"(d[1]), "+f"(d[2]), "+f"(d[3])
        : "r"(a[0]), "r"(a[1]), "r"(a[2]), "r"(a[3]), "r"(b[0]), "r"(b[1]));
}

// ---------------------------------------------------------------------------
// Kernel 1: fold + LayerNorm + projection GEMM (bf16 mma m16n8k16).
// grid=(768,3), block=256 (8 warps). Block tile 64 rows x 128 cols.
// smem (uint32 words): Xs 64x68 (2 bf16/word along K) + W2 64x136 (K-pairs
// packed per word: {W[2k2][n], W[2k2+1][n]}) = 52224 B -> 3 CTAs/SM.
// ---------------------------------------------------------------------------
#define XS_STR 68      // words per Xs row (64 data + 4 pad): (4g+c)%32 distinct
#define W2_STR 136     // words per W2 row (128 data + 8 pad): (8c+g)%32 distinct
#define K1_SMEM ((64*XS_STR + 64*W2_STR) * 4)

__global__ __launch_bounds__(256, 3) void ln_proj_mma(
    const float* __restrict__ q, const float* __restrict__ k, const float* __restrict__ v,
    const float* __restrict__ lnq_g, const float* __restrict__ lnq_b,
    const float* __restrict__ lnk_g, const float* __restrict__ lnk_b,
    const float* __restrict__ lnv_g, const float* __restrict__ lnv_b,
    const float* __restrict__ wq, const float* __restrict__ bq,
    const float* __restrict__ wk, const float* __restrict__ bk,
    const float* __restrict__ wv, const float* __restrict__ bv)
{
    extern __shared__ uint32_t smw[];
    uint32_t* Xs = smw;                  // 64 x 68
    uint32_t* W2 = smw + 64 * XS_STR;    // 64 x 136

    const float* src; const float* gam; const float* bet;
    const float* W; const float* bias; uint32_t* dst;
    int mat = blockIdx.y;
    if (mat == 0)      { src = q; gam = lnq_g; bet = lnq_b; W = wq; bias = bq; dst = g_qp; }
    else if (mat == 1) { src = k; gam = lnk_g; bet = lnk_b; W = wk; bias = bk; dst = g_kp; }
    else               { src = v; gam = lnv_g; bet = lnv_b; W = wv; bias = bv; dst = g_vp; }

    int tid  = threadIdx.x;
    int warp = tid >> 5;
    int lane = tid & 31;
    int row0 = blockIdx.x * 64;

    // Load W, pack K-pairs: W2[k2][n] = {W[2k2][n] lo, W[2k2+1][n] hi}
    for (int i = tid; i < 64 * 128; i += 256) {
        int k2 = i >> 7, n = i & 127;
        float w0 = W[(2 * k2) * 128 + n];
        float w1 = W[(2 * k2 + 1) * 128 + n];
        W2[k2 * W2_STR + n] = packbf(w0, w1);
    }

    // LayerNorm 64 tokens: warp per token
    float4 gg  = ((const float4*)gam)[lane];
    float4 bb4 = ((const float4*)bet)[lane];
    #pragma unroll
    for (int it = 0; it < 8; ++it) {
        int rloc = it * 8 + warp;
        int r = row0 + rloc;
        int bIdx = r / (LWIN * QTOK);
        int rem  = r % (LWIN * QTOK);
        int l = rem / QTOK;
        int t = rem % QTOK;
        int x = l >> 3, y = l & 7;
        int n = t / 64; int w12 = t & 63; int w1 = w12 >> 3, w2 = w12 & 7;
        int srcOff = (((((bIdx * NVIEW + n) * XD + x) * YD + y) * W1D + w1) * W2D + w2) * DIM;

        float4 xv = ((const float4*)(src + srcOff))[lane];
        float s  = xv.x + xv.y + xv.z + xv.w;
        float ss = xv.x * xv.x + xv.y * xv.y + xv.z * xv.z + xv.w * xv.w;
        #pragma unroll
        for (int o = 16; o; o >>= 1) {
            s  += __shfl_xor_sync(FULLMASK, s,  o);
            ss += __shfl_xor_sync(FULLMASK, ss, o);
        }
        float mu  = s * (1.0f / 128.0f);
        float var = ss * (1.0f / 128.0f) - mu * mu;
        float rs  = rsqrtf(var + EPS);
        float o0 = (xv.x - mu) * rs * gg.x + bb4.x;
        float o1 = (xv.y - mu) * rs * gg.y + bb4.y;
        float o2 = (xv.z - mu) * rs * gg.z + bb4.z;
        float o3 = (xv.w - mu) * rs * gg.w + bb4.w;
        Xs[rloc * XS_STR + lane * 2    ] = packbf(o0, o1);
        Xs[rloc * XS_STR + lane * 2 + 1] = packbf(o2, o3);
    }
    __syncthreads();

    // Warp tile 32 rows x 32 cols: mg = warp>>2, ng = warp&3
    int mg = warp >> 2, ng = warp & 3;
    int g  = lane >> 2, c = lane & 3;

    float acc[2][4][4];
    #pragma unroll
    for (int mt = 0; mt < 2; ++mt)
        #pragma unroll
        for (int nt = 0; nt < 4; ++nt)
            { acc[mt][nt][0]=0.f; acc[mt][nt][1]=0.f; acc[mt][nt][2]=0.f; acc[mt][nt][3]=0.f; }

    #pragma unroll 2
    for (int kst = 0; kst < 8; ++kst) {
        uint32_t a[2][4];
        #pragma unroll
        for (int mt = 0; mt < 2; ++mt) {
            const uint32_t* ap = Xs + (mg * 32 + mt * 16) * XS_STR + kst * 8;
            a[mt][0] = ap[ g      * XS_STR + c    ];
            a[mt][1] = ap[(g + 8) * XS_STR + c    ];
            a[mt][2] = ap[ g      * XS_STR + c + 4];
            a[mt][3] = ap[(g + 8) * XS_STR + c + 4];
        }
        #pragma unroll
        for (int nt = 0; nt < 4; ++nt) {
            int n = ng * 32 + nt * 8 + g;
            uint32_t b[2];
            b[0] = W2[(kst * 8 + c    ) * W2_STR + n];
            b[1] = W2[(kst * 8 + c + 4) * W2_STR + n];
            mma16(acc[0][nt], a[0], b);
            mma16(acc[1][nt], a[1], b);
        }
    }

    // Epilogue: + bias, pack bf16x2, store
    #pragma unroll
    for (int nt = 0; nt < 4; ++nt) {
        int col = ng * 32 + nt * 8 + c * 2;
        float2 bv2 = *(const float2*)(bias + col);
        int wcol = ng * 16 + nt * 4 + c;
        #pragma unroll
        for (int mt = 0; mt < 2; ++mt) {
            int rr = row0 + mg * 32 + mt * 16 + g;
            dst[(size_t)rr * 64 + wcol]       = packbf(acc[mt][nt][0] + bv2.x, acc[mt][nt][1] + bv2.y);
            dst[(size_t)(rr + 8) * 64 + wcol] = packbf(acc[mt][nt][2] + bv2.x, acc[mt][nt][3] + bv2.y);
        }
    }
}

// ---------------------------------------------------------------------------
// Kernel 2: flash attention, bf16 mma. 2 blocks per (b,l,head), 192 q rows
// each (12 warps x 16 rows). grid=1024, block=384.
// smem words: Ksm 384x20 (16 data + 4 pad; (20g+c)%32 distinct)
//           + V2 192x40 (V K-pairs packed; 32 data + 8 pad; (8c+g)%32 distinct)
// = 61440 B. P repack is pure register packing (no shuffles).
// ---------------------------------------------------------------------------
#define KS_STR 20
#define V2_STR 40
#define K2_SMEM ((QTOK*KS_STR + (QTOK/2)*V2_STR) * 4)

__global__ __launch_bounds__(384, 2) void attn_mma()
{
    extern __shared__ uint32_t smw[];
    uint32_t* Ksm = smw;                    // 384 x 20
    uint32_t* V2  = smw + QTOK * KS_STR;    // 192 x 40

    int bx   = blockIdx.x;
    int bl   = bx >> 3;
    int m    = (bx >> 1) & 3;
    int half = bx & 1;
    size_t base_w = (size_t)bl * QTOK * 64 + m * 16;   // word offset of head slice

    int tid = threadIdx.x, warp = tid >> 5, lane = tid & 31;
    int g = lane >> 2, c = lane & 3;

    // softmax scale folded with log2(e)
    const float sc = 0.1767766952966369f * 1.4426950408889634f;

    // Fill K: plain rows (16 words of bf16x2 along dhead)
    for (int i = tid; i < QTOK * 16; i += 384) {
        int row = i >> 4, w = i & 15;
        Ksm[row * KS_STR + w] = g_kp[base_w + (size_t)row * 64 + w];
    }
    // Fill V2: key-pair packing. word {V[2r2][n] lo, V[2r2+1][n] hi}
    for (int i = tid; i < (QTOK / 2) * 16; i += 384) {
        int r2 = i >> 4, w = i & 15;
        uint32_t u0 = g_vp[base_w + (size_t)(2 * r2)     * 64 + w];
        uint32_t u1 = g_vp[base_w + (size_t)(2 * r2 + 1) * 64 + w];
        V2[r2 * V2_STR + 2 * w    ] = __byte_perm(u0, u1, 0x5410);  // n = 2w
        V2[r2 * V2_STR + 2 * w + 1] = __byte_perm(u0, u1, 0x7632);  // n = 2w+1
    }

    // Q fragments straight from gmem (16 rows per warp)
    int q0 = half * 192 + warp * 16;
    uint32_t qa[2][4];
    {
        const uint32_t* qr0 = g_qp + base_w + (size_t)(q0 + g) * 64;
        const uint32_t* qr1 = g_qp + base_w + (size_t)(q0 + g + 8) * 64;
        #pragma unroll
        for (int kst = 0; kst < 2; ++kst) {
            qa[kst][0] = qr0[kst * 8 + c    ];
            qa[kst][1] = qr1[kst * 8 + c    ];
            qa[kst][2] = qr0[kst * 8 + c + 4];
            qa[kst][3] = qr1[kst * 8 + c + 4];
        }
    }
    __syncthreads();

    float o[4][4];
    #pragma unroll
    for (int nt = 0; nt < 4; ++nt)
        { o[nt][0]=0.f; o[nt][1]=0.f; o[nt][2]=0.f; o[nt][3]=0.f; }
    float mrun0 = -1e30f, mrun1 = -1e30f;
    float lrun0 = 0.f, lrun1 = 0.f;

    for (int kc = 0; kc < QTOK; kc += 32) {
        // S = Q K^T for 32 keys (scaled)
        float s[4][4];
        #pragma unroll
        for (int nt = 0; nt < 4; ++nt)
            { s[nt][0]=0.f; s[nt][1]=0.f; s[nt][2]=0.f; s[nt][3]=0.f; }

        #pragma unroll
        for (int kst = 0; kst < 2; ++kst) {
            #pragma unroll
            for (int nt = 0; nt < 4; ++nt) {
                const uint32_t* kr = Ksm + (kc + nt * 8 + g) * KS_STR + kst * 8;
                uint32_t b[2] = { kr[c], kr[c + 4] };
                mma16(s[nt], qa[kst], b);
            }
        }
        #pragma unroll
        for (int nt = 0; nt < 4; ++nt) {
            s[nt][0] *= sc; s[nt][1] *= sc; s[nt][2] *= sc; s[nt][3] *= sc;
        }

        // Online softmax (exp2 domain)
        float cm0 = s[0][0], cm1 = s[0][2];
        #pragma unroll
        for (int nt = 0; nt < 4; ++nt) {
            cm0 = fmaxf(cm0, fmaxf(s[nt][0], s[nt][1]));
            cm1 = fmaxf(cm1, fmaxf(s[nt][2], s[nt][3]));
        }
        cm0 = fmaxf(cm0, __shfl_xor_sync(FULLMASK, cm0, 1));
        cm0 = fmaxf(cm0, __shfl_xor_sync(FULLMASK, cm0, 2));
        cm1 = fmaxf(cm1, __shfl_xor_sync(FULLMASK, cm1, 1));
        cm1 = fmaxf(cm1, __shfl_xor_sync(FULLMASK, cm1, 2));
        float mn0 = fmaxf(mrun0, cm0);
        float mn1 = fmaxf(mrun1, cm1);
        float f0 = exp2f(mrun0 - mn0);
        float f1 = exp2f(mrun1 - mn1);
        float rs0 = 0.f, rs1 = 0.f;
        #pragma unroll
        for (int nt = 0; nt < 4; ++nt) {
            s[nt][0] = exp2f(s[nt][0] - mn0);
            s[nt][1] = exp2f(s[nt][1] - mn0);
            s[nt][2] = exp2f(s[nt][2] - mn1);
            s[nt][3] = exp2f(s[nt][3] - mn1);
            rs0 += s[nt][0] + s[nt][1];
            rs1 += s[nt][2] + s[nt][3];
        }
        rs0 += __shfl_xor_sync(FULLMASK, rs0, 1);
        rs0 += __shfl_xor_sync(FULLMASK, rs0, 2);
        rs1 += __shfl_xor_sync(FULLMASK, rs1, 1);
        rs1 += __shfl_xor_sync(FULLMASK, rs1, 2);
        lrun0 = lrun0 * f0 + rs0;
        lrun1 = lrun1 * f1 + rs1;
        mrun0 = mn0; mrun1 = mn1;
        #pragma unroll
        for (int nt = 0; nt < 4; ++nt) {
            o[nt][0] *= f0; o[nt][1] *= f0;
            o[nt][2] *= f1; o[nt][3] *= f1;
        }

        // P repack: D-frag col pairs == A-frag k pairs -> pure register pack
        #pragma unroll
        for (int kt = 0; kt < 2; ++kt) {
            uint32_t pa[4];
            pa[0] = packbf(s[2*kt  ][0], s[2*kt  ][1]);  // row g,   k 2c,2c+1
            pa[1] = packbf(s[2*kt  ][2], s[2*kt  ][3]);  // row g+8
            pa[2] = packbf(s[2*kt+1][0], s[2*kt+1][1]);  // row g,   k 2c+8,2c+9
            pa[3] = packbf(s[2*kt+1][2], s[2*kt+1][3]);  // row g+8
            int r2base = kc / 2 + kt * 8;
            #pragma unroll
            for (int nt = 0; nt < 4; ++nt) {
                int n = nt * 8 + g;
                uint32_t vb[2];
                vb[0] = V2[(r2base + c    ) * V2_STR + n];
                vb[1] = V2[(r2base + c + 4) * V2_STR + n];
                mma16(o[nt], pa, vb);
            }
        }
    }

    // Finalize: divide by l, pack bf16, store
    float inv0 = 1.0f / lrun0;
    float inv1 = 1.0f / lrun1;
    int r0 = q0 + g;
    #pragma unroll
    for (int nt = 0; nt < 4; ++nt) {
        int wcol = nt * 4 + c;
        g_at[base_w + (size_t)r0 * 64 + wcol]       = packbf(o[nt][0] * inv0, o[nt][1] * inv0);
        g_at[base_w + (size_t)(r0 + 8) * 64 + wcol] = packbf(o[nt][2] * inv1, o[nt][3] * inv1);
    }
}

// ---------------------------------------------------------------------------
// Kernel 3: fused mean-over-views (bf16 in) + output projection + bias + skip.
// ---------------------------------------------------------------------------
__global__ __launch_bounds__(256) void out_proj_kernel(
    const float* __restrict__ wp, const float* __restrict__ bp,
    const float* __restrict__ skip, float* __restrict__ out)
{
    extern __shared__ float sm[];
    float* Xs = sm;                 // 64*128
    float* Ws = sm + 64 * 128;      // 128*128

    int tid  = threadIdx.x;
    int row0 = blockIdx.x * 64;

    for (int i = tid; i < 128 * 32; i += 256)
        ((float4*)Ws)[i] = ((const float4*)wp)[i];

    // Xs = mean over n (bf16 source)
    for (int i = tid; i < 64 * 32; i += 256) {
        int rloc = i >> 5, cq = i & 31;      // 4-col group
        int r2 = row0 + rloc;
        int bl = r2 >> 6;
        int w  = r2 & 63;
        float4 a; a.x = 0.f; a.y = 0.f; a.z = 0.f; a.w = 0.f;
        #pragma unroll
        for (int n = 0; n < NVIEW; ++n) {
            const uint32_t* p = g_at + (size_t)(bl * QTOK + n * 64 + w) * 64 + cq * 2;
            uint32_t u0 = p[0], u1 = p[1];
            a.x += bflo(u0); a.y += bfhi(u0);
            a.z += bflo(u1); a.w += bfhi(u1);
        }
        const float invn = 1.0f / 6.0f;
        a.x *= invn; a.y *= invn; a.z *= invn; a.w *= invn;
        ((float4*)Xs)[rloc * 32 + cq] = a;
    }
    __syncthreads();

    int ti = tid >> 5;
    int cj = tid & 31;
    float acc[8][4];
    #pragma unroll
    for (int i = 0; i < 8; ++i) { acc[i][0]=0.f; acc[i][1]=0.f; acc[i][2]=0.f; acc[i][3]=0.f; }

    const float4* Ws4 = (const float4*)Ws;
    #pragma unroll 8
    for (int kk = 0; kk < 128; ++kk) {
        float4 wv = Ws4[kk * 32 + cj];
        #pragma unroll
        for (int i = 0; i < 8; ++i) {
            float xv = Xs[(ti * 8 + i) * 128 + kk];
            acc[i][0] += xv * wv.x;
            acc[i][1] += xv * wv.y;
            acc[i][2] += xv * wv.z;
            acc[i][3] += xv * wv.w;
        }
    }

    float4 bsv = ((const float4*)bp)[cj];
    #pragma unroll
    for (int i = 0; i < 8; ++i) {
        int r = row0 + ti * 8 + i;
        float4 sk = ((const float4*)(skip + (size_t)r * 128))[cj];
        float4 o;
        o.x = acc[i][0] + bsv.x + sk.x;
        o.y = acc[i][1] + bsv.y + sk.y;
        o.z = acc[i][2] + bsv.z + sk.z;
        o.w = acc[i][3] + bsv.w + sk.w;
        ((float4*)(out + (size_t)r * 128))[cj] = o;
    }
}

// ---------------------------------------------------------------------------
extern "C" void kernel_launch(void* const* d_in, const int* in_sizes, int n_in,
                              void* d_out, int out_size)
{
    const float* q     = (const float*)d_in[0];
    const float* k     = (const float*)d_in[1];
    const float* v     = (const float*)d_in[2];
    const float* skip  = (const float*)d_in[3];
    const float* lnq_g = (const float*)d_in[4];
    const float* lnq_b = (const float*)d_in[5];
    const float* lnk_g = (const float*)d_in[6];
    const float* lnk_b = (const float*)d_in[7];
    const float* lnv_g = (const float*)d_in[8];
    const float* lnv_b = (const float*)d_in[9];
    const float* wq    = (const float*)d_in[10];
    const float* bq    = (const float*)d_in[11];
    const float* wk    = (const float*)d_in[12];
    const float* bk    = (const float*)d_in[13];
    const float* wv    = (const float*)d_in[14];
    const float* bv    = (const float*)d_in[15];
    const float* wp    = (const float*)d_in[16];
    const float* bp    = (const float*)d_in[17];
    float* out = (float*)d_out;

    cudaFuncSetAttribute(ln_proj_mma,     cudaFuncAttributeMaxDynamicSharedMemorySize, K1_SMEM);
    cudaFuncSetAttribute(attn_mma,        cudaFuncAttributeMaxDynamicSharedMemorySize, K2_SMEM);
    cudaFuncSetAttribute(out_proj_kernel, cudaFuncAttributeMaxDynamicSharedMemorySize, 96 * 1024);

    ln_proj_mma<<<dim3(TOKENS / 64, 3), 256, K1_SMEM>>>(
        q, k, v, lnq_g, lnq_b, lnk_g, lnk_b, lnv_g, lnv_b,
        wq, bq, wk, bk, wv, bv);

    attn_mma<<<NBL * HEADS * 2, 384, K2_SMEM>>>();

    out_proj_kernel<<<R2ROWS / 64, 256, 96 * 1024>>>(wp, bp, skip, out);
}

// round 5
// speedup vs baseline: 3.9819x; 1.0137x over previous
#include <cuda_runtime.h>
#include <cstdint>

// Problem constants
#define BATCH   2
#define NVIEW   6
#define XD      8
#define YD      8
#define W1D     8
#define W2D     8
#define DIM     128
#define HEADS   4
#define DHEAD   32
#define HDIM    128
#define LWIN    64
#define QTOK    384
#define NBL     128
#define TOKENS  49152
#define R2ROWS  8192
#define EPS     1e-5f
#define FULLMASK 0xffffffffu

// Scratch: bf16 intermediates packed as uint32 (2 bf16/word, 64 words/row)
__device__ uint32_t g_qp[TOKENS * 64];
__device__ uint32_t g_kp[TOKENS * 64];
__device__ uint32_t g_vp[TOKENS * 64];
__device__ uint32_t g_at[TOKENS * 64];

__device__ __forceinline__ uint32_t packbf(float lo, float hi) {
    uint32_t d;
    asm("cvt.rn.bf16x2.f32 %0, %1, %2;" : "=r"(d) : "f"(hi), "f"(lo));
    return d;
}
__device__ __forceinline__ float bflo(uint32_t u) { return __uint_as_float(u << 16); }
__device__ __forceinline__ float bfhi(uint32_t u) { return __uint_as_float(u & 0xffff0000u); }

// D += A(16x16) * B(16x8), bf16 inputs, fp32 accum
__device__ __forceinline__ void mma16(float* d, const uint32_t* a, const uint32_t* b) {
    asm volatile("mma.sync.aligned.m16n8k16.row.col.f32.bf16.bf16.f32 "
        "{%0,%1,%2,%3}, {%4,%5,%6,%7}, {%8,%9}, {%0,%1,%2,%3};"
        : "+f"(d[0]), "+f"(d[1]), "+f"(d[2]), "+f"(d[3])
        : "r"(a[0]), "r"(a[1]), "r"(a[2]), "r"(a[3]), "r"(b[0]), "r"(b[1]));
}
// ldmatrix x4: 4 8x8 b16 tiles -> 4 regs/thread
__device__ __forceinline__ void ldsm4(uint32_t* r, uint32_t saddr) {
    asm volatile("ldmatrix.sync.aligned.m8n8.x4.shared.b16 {%0,%1,%2,%3}, [%4];"
        : "=r"(r[0]), "=r"(r[1]), "=r"(r[2]), "=r"(r[3]) : "r"(saddr));
}

// ---------------------------------------------------------------------------
// Kernel 1: fold + LayerNorm + projection GEMM (bf16 mma + ldmatrix).
// grid=(768,3), block=256 (8 warps). Block tile 64 rows x 128 cols.
// smem bf16: Xs 64 x 136  (tokens x K)    17408 B
//            Wt 128 x 136 (N x K, transposed weights) 34816 B
// stride 136 bf16 = 272 B = 68 words; 68r mod 32 = 4r -> ldmatrix conflict-free.
// ---------------------------------------------------------------------------
#define XS_WSTR 68
#define XS_BSTR 272
#define WT_WOFF (64 * XS_WSTR)
#define WT_BOFF (64 * XS_BSTR)
#define K1_SMEM ((64 + 128) * XS_BSTR)

__global__ __launch_bounds__(256, 3) void ln_proj_mma(
    const float* __restrict__ q, const float* __restrict__ k, const float* __restrict__ v,
    const float* __restrict__ lnq_g, const float* __restrict__ lnq_b,
    const float* __restrict__ lnk_g, const float* __restrict__ lnk_b,
    const float* __restrict__ lnv_g, const float* __restrict__ lnv_b,
    const float* __restrict__ wq, const float* __restrict__ bq,
    const float* __restrict__ wk, const float* __restrict__ bk,
    const float* __restrict__ wv, const float* __restrict__ bv)
{
    extern __shared__ uint32_t smw[];
    uint32_t sbase = (uint32_t)__cvta_generic_to_shared(smw);

    const float* src; const float* gam; const float* bet;
    const float* W; const float* bias; uint32_t* dst;
    int mat = blockIdx.y;
    if (mat == 0)      { src = q; gam = lnq_g; bet = lnq_b; W = wq; bias = bq; dst = g_qp; }
    else if (mat == 1) { src = k; gam = lnk_g; bet = lnk_b; W = wk; bias = bk; dst = g_kp; }
    else               { src = v; gam = lnv_g; bet = lnv_b; W = wv; bias = bv; dst = g_vp; }

    int tid  = threadIdx.x;
    int warp = tid >> 5;
    int lane = tid & 31;
    int row0 = blockIdx.x * 64;

    // Wt fill: Wt[n][k] = W[k][n], packed k-pairs per word at word n*68 + k2
    for (int i = tid; i < 64 * 128; i += 256) {
        int k2 = i >> 7, n = i & 127;
        float w0 = W[(2 * k2) * 128 + n];
        float w1 = W[(2 * k2 + 1) * 128 + n];
        smw[WT_WOFF + n * XS_WSTR + k2] = packbf(w0, w1);
    }

    // LayerNorm 64 tokens: warp per token
    float4 gg  = ((const float4*)gam)[lane];
    float4 bb4 = ((const float4*)bet)[lane];
    #pragma unroll
    for (int it = 0; it < 8; ++it) {
        int rloc = it * 8 + warp;
        int r = row0 + rloc;
        int bIdx = r / (LWIN * QTOK);
        int rem  = r % (LWIN * QTOK);
        int l = rem / QTOK;
        int t = rem % QTOK;
        int x = l >> 3, y = l & 7;
        int n = t / 64; int w12 = t & 63; int w1 = w12 >> 3, w2 = w12 & 7;
        int srcOff = (((((bIdx * NVIEW + n) * XD + x) * YD + y) * W1D + w1) * W2D + w2) * DIM;

        float4 xv = ((const float4*)(src + srcOff))[lane];
        float s  = xv.x + xv.y + xv.z + xv.w;
        float ss = xv.x * xv.x + xv.y * xv.y + xv.z * xv.z + xv.w * xv.w;
        #pragma unroll
        for (int o = 16; o; o >>= 1) {
            s  += __shfl_xor_sync(FULLMASK, s,  o);
            ss += __shfl_xor_sync(FULLMASK, ss, o);
        }
        float mu  = s * (1.0f / 128.0f);
        float var = ss * (1.0f / 128.0f) - mu * mu;
        float rs  = rsqrtf(var + EPS);
        float o0 = (xv.x - mu) * rs * gg.x + bb4.x;
        float o1 = (xv.y - mu) * rs * gg.y + bb4.y;
        float o2 = (xv.z - mu) * rs * gg.z + bb4.z;
        float o3 = (xv.w - mu) * rs * gg.w + bb4.w;
        smw[rloc * XS_WSTR + lane * 2    ] = packbf(o0, o1);
        smw[rloc * XS_WSTR + lane * 2 + 1] = packbf(o2, o3);
    }
    __syncthreads();

    // Warp tile 32 rows x 32 cols: mg = warp>>2, ng = warp&3
    int mg = warp >> 2, ng = warp & 3;
    int g  = lane >> 2, c = lane & 3;

    float acc[2][4][4];
    #pragma unroll
    for (int mt = 0; mt < 2; ++mt)
        #pragma unroll
        for (int nt = 0; nt < 4; ++nt)
            { acc[mt][nt][0]=0.f; acc[mt][nt][1]=0.f; acc[mt][nt][2]=0.f; acc[mt][nt][3]=0.f; }

    // ldmatrix base addresses
    int khi = (lane & 16) >> 1;                 // +8 k for lanes 16-31
    uint32_t aA0 = sbase + (mg * 32 + (lane & 15)) * XS_BSTR + khi * 2;
    uint32_t aA1 = aA0 + 16 * XS_BSTR;
    uint32_t aB0 = sbase + WT_BOFF
                 + (ng * 32 + (lane & 7) + khi) * XS_BSTR + (lane & 8) * 2;
    uint32_t aB1 = aB0 + 16 * XS_BSTR;

    #pragma unroll
    for (int kst = 0; kst < 8; ++kst) {
        uint32_t a0[4], a1[4], b0[4], b1[4];
        ldsm4(a0, aA0 + kst * 32);
        ldsm4(a1, aA1 + kst * 32);
        ldsm4(b0, aB0 + kst * 32);
        ldsm4(b1, aB1 + kst * 32);
        mma16(acc[0][0], a0, b0);     mma16(acc[0][1], a0, b0 + 2);
        mma16(acc[0][2], a0, b1);     mma16(acc[0][3], a0, b1 + 2);
        mma16(acc[1][0], a1, b0);     mma16(acc[1][1], a1, b0 + 2);
        mma16(acc[1][2], a1, b1);     mma16(acc[1][3], a1, b1 + 2);
    }

    // Epilogue: + bias, pack bf16x2, store
    #pragma unroll
    for (int nt = 0; nt < 4; ++nt) {
        int col = ng * 32 + nt * 8 + c * 2;
        float2 bv2 = *(const float2*)(bias + col);
        int wcol = ng * 16 + nt * 4 + c;
        #pragma unroll
        for (int mt = 0; mt < 2; ++mt) {
            int rr = row0 + mg * 32 + mt * 16 + g;
            dst[(size_t)rr * 64 + wcol]       = packbf(acc[mt][nt][0] + bv2.x, acc[mt][nt][1] + bv2.y);
            dst[(size_t)(rr + 8) * 64 + wcol] = packbf(acc[mt][nt][2] + bv2.x, acc[mt][nt][3] + bv2.y);
        }
    }
}

// ---------------------------------------------------------------------------
// Kernel 2: flash attention, bf16 mma + ldmatrix. 2 blocks per (b,l,head),
// 192 q rows each (12 warps x 16 rows). grid=1024, block=384.
// smem bf16: Ksm 384 x 40 (key-major, stride 20 words -> 20r%32 conflict-free)
//            Vt  32 x 392 (dim-major V^T, stride 196 words -> 4r%32 pattern)
// = 55808 B -> 2 CTAs/SM (24 warps).
// ---------------------------------------------------------------------------
#define KS_WSTR 20
#define KS_BSTR 80
#define VT_WOFF (QTOK * KS_WSTR)
#define VT_BOFF (QTOK * KS_BSTR)
#define VT_WSTR 196
#define VT_BSTR 784
#define K2_SMEM (VT_BOFF + 32 * VT_BSTR)

__global__ __launch_bounds__(384, 2) void attn_mma()
{
    extern __shared__ uint32_t smw[];
    uint32_t sbase = (uint32_t)__cvta_generic_to_shared(smw);

    int bx   = blockIdx.x;
    int bl   = bx >> 3;
    int m    = (bx >> 1) & 3;
    int half = bx & 1;
    size_t base_w = (size_t)bl * QTOK * 64 + m * 16;   // word offset of head slice

    int tid = threadIdx.x, warp = tid >> 5, lane = tid & 31;
    int g = lane >> 2, c = lane & 3;

    const float sc = 0.1767766952966369f * 1.4426950408889634f;  // scale * log2(e)

    // Fill K: row = key, 16 bf16x2 words of dims
    for (int i = tid; i < QTOK * 16; i += 384) {
        int row = i >> 4, w = i & 15;
        smw[row * KS_WSTR + w] = g_kp[base_w + (size_t)row * 64 + w];
    }
    // Fill Vt: Vt[dim][key] bf16; word (d, keypair r2) at d*196 + r2
    for (int i = tid; i < (QTOK / 2) * 16; i += 384) {
        int r2 = i >> 4, w = i & 15;
        uint32_t u0 = g_vp[base_w + (size_t)(2 * r2)     * 64 + w];
        uint32_t u1 = g_vp[base_w + (size_t)(2 * r2 + 1) * 64 + w];
        smw[VT_WOFF + (2 * w)     * VT_WSTR + r2] = __byte_perm(u0, u1, 0x5410);
        smw[VT_WOFF + (2 * w + 1) * VT_WSTR + r2] = __byte_perm(u0, u1, 0x7632);
    }

    // Q fragments straight from gmem (16 rows per warp)
    int q0 = half * 192 + warp * 16;
    uint32_t qa[2][4];
    {
        const uint32_t* qr0 = g_qp + base_w + (size_t)(q0 + g) * 64;
        const uint32_t* qr1 = g_qp + base_w + (size_t)(q0 + g + 8) * 64;
        #pragma unroll
        for (int kst = 0; kst < 2; ++kst) {
            qa[kst][0] = qr0[kst * 8 + c    ];
            qa[kst][1] = qr1[kst * 8 + c    ];
            qa[kst][2] = qr0[kst * 8 + c + 4];
            qa[kst][3] = qr1[kst * 8 + c + 4];
        }
    }
    __syncthreads();

    float o[4][4];
    #pragma unroll
    for (int nt = 0; nt < 4; ++nt)
        { o[nt][0]=0.f; o[nt][1]=0.f; o[nt][2]=0.f; o[nt][3]=0.f; }
    float mrun0 = -1e30f, mrun1 = -1e30f;
    float lrun0 = 0.f, lrun1 = 0.f;

    // ldmatrix lane geometry
    int rhi = (lane & 16) >> 1;                       // +8 rows for lanes 16-31
    uint32_t aK = sbase + ((lane & 7) + rhi) * KS_BSTR + (lane & 8) * 2;
    uint32_t aV = sbase + VT_BOFF + ((lane & 7) + rhi) * VT_BSTR + (lane & 8) * 2;

    for (int kc = 0; kc < QTOK; kc += 32) {
        // S = Q K^T for 32 keys
        float s[4][4];
        #pragma unroll
        for (int nt = 0; nt < 4; ++nt)
            { s[nt][0]=0.f; s[nt][1]=0.f; s[nt][2]=0.f; s[nt][3]=0.f; }

        #pragma unroll
        for (int kst = 0; kst < 2; ++kst) {
            uint32_t b0[4], b1[4];
            ldsm4(b0, aK + (kc)      * KS_BSTR + kst * 32);   // key tiles 0,1
            ldsm4(b1, aK + (kc + 16) * KS_BSTR + kst * 32);   // key tiles 2,3
            mma16(s[0], qa[kst], b0);     mma16(s[1], qa[kst], b0 + 2);
            mma16(s[2], qa[kst], b1);     mma16(s[3], qa[kst], b1 + 2);
        }
        #pragma unroll
        for (int nt = 0; nt < 4; ++nt) {
            s[nt][0] *= sc; s[nt][1] *= sc; s[nt][2] *= sc; s[nt][3] *= sc;
        }

        // Online softmax (exp2 domain)
        float cm0 = s[0][0], cm1 = s[0][2];
        #pragma unroll
        for (int nt = 0; nt < 4; ++nt) {
            cm0 = fmaxf(cm0, fmaxf(s[nt][0], s[nt][1]));
            cm1 = fmaxf(cm1, fmaxf(s[nt][2], s[nt][3]));
        }
        cm0 = fmaxf(cm0, __shfl_xor_sync(FULLMASK, cm0, 1));
        cm0 = fmaxf(cm0, __shfl_xor_sync(FULLMASK, cm0, 2));
        cm1 = fmaxf(cm1, __shfl_xor_sync(FULLMASK, cm1, 1));
        cm1 = fmaxf(cm1, __shfl_xor_sync(FULLMASK, cm1, 2));
        float mn0 = fmaxf(mrun0, cm0);
        float mn1 = fmaxf(mrun1, cm1);
        float f0 = exp2f(mrun0 - mn0);
        float f1 = exp2f(mrun1 - mn1);
        float rs0 = 0.f, rs1 = 0.f;
        #pragma unroll
        for (int nt = 0; nt < 4; ++nt) {
            s[nt][0] = exp2f(s[nt][0] - mn0);
            s[nt][1] = exp2f(s[nt][1] - mn0);
            s[nt][2] = exp2f(s[nt][2] - mn1);
            s[nt][3] = exp2f(s[nt][3] - mn1);
            rs0 += s[nt][0] + s[nt][1];
            rs1 += s[nt][2] + s[nt][3];
        }
        rs0 += __shfl_xor_sync(FULLMASK, rs0, 1);
        rs0 += __shfl_xor_sync(FULLMASK, rs0, 2);
        rs1 += __shfl_xor_sync(FULLMASK, rs1, 1);
        rs1 += __shfl_xor_sync(FULLMASK, rs1, 2);
        lrun0 = lrun0 * f0 + rs0;
        lrun1 = lrun1 * f1 + rs1;
        mrun0 = mn0; mrun1 = mn1;
        #pragma unroll
        for (int nt = 0; nt < 4; ++nt) {
            o[nt][0] *= f0; o[nt][1] *= f0;
            o[nt][2] *= f1; o[nt][3] *= f1;
        }

        // O += P V : pack P into A-fragments (register-only), ldmatrix Vt
        #pragma unroll
        for (int kt = 0; kt < 2; ++kt) {
            uint32_t pa[4];
            pa[0] = packbf(s[2*kt  ][0], s[2*kt  ][1]);
            pa[1] = packbf(s[2*kt  ][2], s[2*kt  ][3]);
            pa[2] = packbf(s[2*kt+1][0], s[2*kt+1][1]);
            pa[3] = packbf(s[2*kt+1][2], s[2*kt+1][3]);
            int kbase = kc + kt * 16;
            uint32_t v0[4], v1[4];
            ldsm4(v0, aV           + kbase * 2);     // dim tiles 0,1
            ldsm4(v1, aV + 16 * VT_BSTR + kbase * 2); // dim tiles 2,3
            mma16(o[0], pa, v0);     mma16(o[1], pa, v0 + 2);
            mma16(o[2], pa, v1);     mma16(o[3], pa, v1 + 2);
        }
    }

    // Finalize: divide by l, pack bf16, store
    float inv0 = 1.0f / lrun0;
    float inv1 = 1.0f / lrun1;
    int r0 = q0 + g;
    #pragma unroll
    for (int nt = 0; nt < 4; ++nt) {
        int wcol = nt * 4 + c;
        g_at[base_w + (size_t)r0 * 64 + wcol]       = packbf(o[nt][0] * inv0, o[nt][1] * inv0);
        g_at[base_w + (size_t)(r0 + 8) * 64 + wcol] = packbf(o[nt][2] * inv1, o[nt][3] * inv1);
    }
}

// ---------------------------------------------------------------------------
// Kernel 3: fused mean-over-views (bf16 in) + output projection + bias + skip.
// ---------------------------------------------------------------------------
__global__ __launch_bounds__(256) void out_proj_kernel(
    const float* __restrict__ wp, const float* __restrict__ bp,
    const float* __restrict__ skip, float* __restrict__ out)
{
    extern __shared__ float sm[];
    float* Xs = sm;                 // 64*128
    float* Ws = sm + 64 * 128;      // 128*128

    int tid  = threadIdx.x;
    int row0 = blockIdx.x * 64;

    for (int i = tid; i < 128 * 32; i += 256)
        ((float4*)Ws)[i] = ((const float4*)wp)[i];

    for (int i = tid; i < 64 * 32; i += 256) {
        int rloc = i >> 5, cq = i & 31;
        int r2 = row0 + rloc;
        int bl = r2 >> 6;
        int w  = r2 & 63;
        float4 a; a.x = 0.f; a.y = 0.f; a.z = 0.f; a.w = 0.f;
        #pragma unroll
        for (int n = 0; n < NVIEW; ++n) {
            const uint32_t* p = g_at + (size_t)(bl * QTOK + n * 64 + w) * 64 + cq * 2;
            uint32_t u0 = p[0], u1 = p[1];
            a.x += bflo(u0); a.y += bfhi(u0);
            a.z += bflo(u1); a.w += bfhi(u1);
        }
        const float invn = 1.0f / 6.0f;
        a.x *= invn; a.y *= invn; a.z *= invn; a.w *= invn;
        ((float4*)Xs)[rloc * 32 + cq] = a;
    }
    __syncthreads();

    int ti = tid >> 5;
    int cj = tid & 31;
    float acc[8][4];
    #pragma unroll
    for (int i = 0; i < 8; ++i) { acc[i][0]=0.f; acc[i][1]=0.f; acc[i][2]=0.f; acc[i][3]=0.f; }

    const float4* Ws4 = (const float4*)Ws;
    #pragma unroll 8
    for (int kk = 0; kk < 128; ++kk) {
        float4 wv = Ws4[kk * 32 + cj];
        #pragma unroll
        for (int i = 0; i < 8; ++i) {
            float xv = Xs[(ti * 8 + i) * 128 + kk];
            acc[i][0] += xv * wv.x;
            acc[i][1] += xv * wv.y;
            acc[i][2] += xv * wv.z;
            acc[i][3] += xv * wv.w;
        }
    }

    float4 bsv = ((const float4*)bp)[cj];
    #pragma unroll
    for (int i = 0; i < 8; ++i) {
        int r = row0 + ti * 8 + i;
        float4 sk = ((const float4*)(skip + (size_t)r * 128))[cj];
        float4 o;
        o.x = acc[i][0] + bsv.x + sk.x;
        o.y = acc[i][1] + bsv.y + sk.y;
        o.z = acc[i][2] + bsv.z + sk.z;
        o.w = acc[i][3] + bsv.w + sk.w;
        ((float4*)(out + (size_t)r * 128))[cj] = o;
    }
}

// ---------------------------------------------------------------------------
extern "C" void kernel_launch(void* const* d_in, const int* in_sizes, int n_in,
                              void* d_out, int out_size)
{
    const float* q     = (const float*)d_in[0];
    const float* k     = (const float*)d_in[1];
    const float* v     = (const float*)d_in[2];
    const float* skip  = (const float*)d_in[3];
    const float* lnq_g = (const float*)d_in[4];
    const float* lnq_b = (const float*)d_in[5];
    const float* lnk_g = (const float*)d_in[6];
    const float* lnk_b = (const float*)d_in[7];
    const float* lnv_g = (const float*)d_in[8];
    const float* lnv_b = (const float*)d_in[9];
    const float* wq    = (const float*)d_in[10];
    const float* bq    = (const float*)d_in[11];
    const float* wk    = (const float*)d_in[12];
    const float* bk    = (const float*)d_in[13];
    const float* wv    = (const float*)d_in[14];
    const float* bv    = (const float*)d_in[15];
    const float* wp    = (const float*)d_in[16];
    const float* bp    = (const float*)d_in[17];
    float* out = (float*)d_out;

    cudaFuncSetAttribute(ln_proj_mma,     cudaFuncAttributeMaxDynamicSharedMemorySize, K1_SMEM);
    cudaFuncSetAttribute(attn_mma,        cudaFuncAttributeMaxDynamicSharedMemorySize, K2_SMEM);
    cudaFuncSetAttribute(out_proj_kernel, cudaFuncAttributeMaxDynamicSharedMemorySize, 96 * 1024);

    ln_proj_mma<<<dim3(TOKENS / 64, 3), 256, K1_SMEM>>>(
        q, k, v, lnq_g, lnq_b, lnk_g, lnk_b, lnv_g, lnv_b,
        wq, bq, wk, bk, wv, bv);

    attn_mma<<<NBL * HEADS * 2, 384, K2_SMEM>>>();

    out_proj_kernel<<<R2ROWS / 64, 256, 96 * 1024>>>(wp, bp, skip, out);
}

// round 6
// speedup vs baseline: 4.1358x; 1.0387x over previous
#include <cuda_runtime.h>
#include <cstdint>

// Problem constants
#define BATCH   2
#define NVIEW   6
#define XD      8
#define YD      8
#define W1D     8
#define W2D     8
#define DIM     128
#define HEADS   4
#define DHEAD   32
#define HDIM    128
#define LWIN    64
#define QTOK    384
#define NBL     128
#define TOKENS  49152
#define R2ROWS  8192
#define EPS     1e-5f
#define FULLMASK 0xffffffffu

// Scratch: bf16 intermediates packed as uint32 (2 bf16/word, 64 words/row)
__device__ uint32_t g_qp[TOKENS * 64];
__device__ uint32_t g_kp[TOKENS * 64];
__device__ uint32_t g_vp[TOKENS * 64];
__device__ uint32_t g_at[TOKENS * 64];
// Pre-packed transposed weights: [mat][n*64 + k2] = {W[2k2][n], W[2k2+1][n]} bf16x2
__device__ uint32_t g_wt[3 * 128 * 64];

__device__ __forceinline__ uint32_t packbf(float lo, float hi) {
    uint32_t d;
    asm("cvt.rn.bf16x2.f32 %0, %1, %2;" : "=r"(d) : "f"(hi), "f"(lo));
    return d;
}
__device__ __forceinline__ float bflo(uint32_t u) { return __uint_as_float(u << 16); }
__device__ __forceinline__ float bfhi(uint32_t u) { return __uint_as_float(u & 0xffff0000u); }

// D += A(16x16) * B(16x8), bf16 inputs, fp32 accum
__device__ __forceinline__ void mma16(float* d, const uint32_t* a, const uint32_t* b) {
    asm volatile("mma.sync.aligned.m16n8k16.row.col.f32.bf16.bf16.f32 "
        "{%0,%1,%2,%3}, {%4,%5,%6,%7}, {%8,%9}, {%0,%1,%2,%3};"
        : "+f"(d[0]), "+f"(d[1]), "+f"(d[2]), "+f"(d[3])
        : "r"(a[0]), "r"(a[1]), "r"(a[2]), "r"(a[3]), "r"(b[0]), "r"(b[1]));
}
__device__ __forceinline__ void ldsm4(uint32_t* r, uint32_t saddr) {
    asm volatile("ldmatrix.sync.aligned.m8n8.x4.shared.b16 {%0,%1,%2,%3}, [%4];"
        : "=r"(r[0]), "=r"(r[1]), "=r"(r[2]), "=r"(r[3]) : "r"(saddr));
}

// ---------------------------------------------------------------------------
// Kernel 0: pre-pack the three projection weight matrices (runs once/launch).
// ---------------------------------------------------------------------------
__global__ __launch_bounds__(256) void pack_w_kernel(
    const float* __restrict__ wq, const float* __restrict__ wk,
    const float* __restrict__ wv)
{
    const float* W = (blockIdx.x == 0) ? wq : (blockIdx.x == 1) ? wk : wv;
    uint32_t* dst = g_wt + blockIdx.x * 8192;
    for (int i = threadIdx.x; i < 8192; i += 256) {
        int k2 = i >> 7, n = i & 127;
        dst[n * 64 + k2] = packbf(W[(2 * k2) * 128 + n], W[(2 * k2 + 1) * 128 + n]);
    }
}

// ---------------------------------------------------------------------------
// Kernel 1: fold + LayerNorm + projection GEMM (bf16 mma + ldmatrix).
// grid=(768,3), block=256 (8 warps). Block tile 64 rows x 128 cols.
// Key fact: 384 = 6*64, so each 64-token tile has fixed (b,l,n) and
// contiguous source rows: srcOff = base + rloc*128.
// smem bf16: Xs 64 x 136, Wt 128 x 136 (stride 68 words, ldmatrix-safe)
// ---------------------------------------------------------------------------
#define XS_WSTR 68
#define XS_BSTR 272
#define WT_WOFF (64 * XS_WSTR)
#define WT_BOFF (64 * XS_BSTR)
#define K1_SMEM ((64 + 128) * XS_BSTR)

__global__ __launch_bounds__(256, 3) void ln_proj_mma(
    const float* __restrict__ q, const float* __restrict__ k, const float* __restrict__ v,
    const float* __restrict__ lnq_g, const float* __restrict__ lnq_b,
    const float* __restrict__ lnk_g, const float* __restrict__ lnk_b,
    const float* __restrict__ lnv_g, const float* __restrict__ lnv_b,
    const float* __restrict__ bq, const float* __restrict__ bk,
    const float* __restrict__ bv)
{
    extern __shared__ uint32_t smw[];
    uint32_t sbase = (uint32_t)__cvta_generic_to_shared(smw);

    const float* src; const float* gam; const float* bet;
    const float* bias; uint32_t* dst;
    int mat = blockIdx.y;
    if (mat == 0)      { src = q; gam = lnq_g; bet = lnq_b; bias = bq; dst = g_qp; }
    else if (mat == 1) { src = k; gam = lnk_g; bet = lnk_b; bias = bk; dst = g_kp; }
    else               { src = v; gam = lnv_g; bet = lnv_b; bias = bv; dst = g_vp; }

    int tid  = threadIdx.x;
    int warp = tid >> 5;
    int lane = tid & 31;
    int row0 = blockIdx.x * 64;

    // Wt fill from pre-packed gmem: 2048 uint4 copies
    {
        const uint4* wsrc = (const uint4*)(g_wt + mat * 8192);
        #pragma unroll
        for (int it = 0; it < 8; ++it) {
            int j  = it * 256 + tid;        // uint4 index
            int n  = j >> 4, c4 = j & 15;
            *(uint4*)(smw + WT_WOFF + n * XS_WSTR + c4 * 4) = wsrc[j];
        }
    }

    // Hoisted fold decode: tile = fixed (b,l,n), contiguous 64x128 source block
    int bIdx = row0 / (LWIN * QTOK);
    int rem  = row0 % (LWIN * QTOK);
    int l = rem / QTOK;
    int t = rem % QTOK;
    int n = t >> 6;
    int x = l >> 3, y = l & 7;
    const float* srcBase = src +
        (size_t)((((bIdx * NVIEW + n) * XD + x) * YD + y)) * (W1D * W2D * DIM);

    // LayerNorm 64 tokens: warp per token, contiguous rows
    float4 gg  = ((const float4*)gam)[lane];
    float4 bb4 = ((const float4*)bet)[lane];
    #pragma unroll
    for (int it = 0; it < 8; ++it) {
        int rloc = it * 8 + warp;
        float4 xv = ((const float4*)(srcBase + rloc * DIM))[lane];
        float s  = xv.x + xv.y + xv.z + xv.w;
        float ss = xv.x * xv.x + xv.y * xv.y + xv.z * xv.z + xv.w * xv.w;
        #pragma unroll
        for (int o = 16; o; o >>= 1) {
            s  += __shfl_xor_sync(FULLMASK, s,  o);
            ss += __shfl_xor_sync(FULLMASK, ss, o);
        }
        float mu  = s * (1.0f / 128.0f);
        float var = ss * (1.0f / 128.0f) - mu * mu;
        float rs  = rsqrtf(var + EPS);
        float o0 = (xv.x - mu) * rs * gg.x + bb4.x;
        float o1 = (xv.y - mu) * rs * gg.y + bb4.y;
        float o2 = (xv.z - mu) * rs * gg.z + bb4.z;
        float o3 = (xv.w - mu) * rs * gg.w + bb4.w;
        smw[rloc * XS_WSTR + lane * 2    ] = packbf(o0, o1);
        smw[rloc * XS_WSTR + lane * 2 + 1] = packbf(o2, o3);
    }
    __syncthreads();

    // Warp tile 32 rows x 32 cols: mg = warp>>2, ng = warp&3
    int mg = warp >> 2, ng = warp & 3;
    int g  = lane >> 2, c = lane & 3;

    float acc[2][4][4];
    #pragma unroll
    for (int mt = 0; mt < 2; ++mt)
        #pragma unroll
        for (int nt = 0; nt < 4; ++nt)
            { acc[mt][nt][0]=0.f; acc[mt][nt][1]=0.f; acc[mt][nt][2]=0.f; acc[mt][nt][3]=0.f; }

    int khi = (lane & 16) >> 1;
    uint32_t aA0 = sbase + (mg * 32 + (lane & 15)) * XS_BSTR + khi * 2;
    uint32_t aA1 = aA0 + 16 * XS_BSTR;
    uint32_t aB0 = sbase + WT_BOFF
                 + (ng * 32 + (lane & 7) + khi) * XS_BSTR + (lane & 8) * 2;
    uint32_t aB1 = aB0 + 16 * XS_BSTR;

    #pragma unroll
    for (int kst = 0; kst < 8; ++kst) {
        uint32_t a0[4], a1[4], b0[4], b1[4];
        ldsm4(a0, aA0 + kst * 32);
        ldsm4(a1, aA1 + kst * 32);
        ldsm4(b0, aB0 + kst * 32);
        ldsm4(b1, aB1 + kst * 32);
        mma16(acc[0][0], a0, b0);     mma16(acc[0][1], a0, b0 + 2);
        mma16(acc[0][2], a0, b1);     mma16(acc[0][3], a0, b1 + 2);
        mma16(acc[1][0], a1, b0);     mma16(acc[1][1], a1, b0 + 2);
        mma16(acc[1][2], a1, b1);     mma16(acc[1][3], a1, b1 + 2);
    }

    // Epilogue: + bias, pack bf16x2, store
    #pragma unroll
    for (int nt = 0; nt < 4; ++nt) {
        int col = ng * 32 + nt * 8 + c * 2;
        float2 bv2 = *(const float2*)(bias + col);
        int wcol = ng * 16 + nt * 4 + c;
        #pragma unroll
        for (int mt = 0; mt < 2; ++mt) {
            int rr = row0 + mg * 32 + mt * 16 + g;
            dst[(size_t)rr * 64 + wcol]       = packbf(acc[mt][nt][0] + bv2.x, acc[mt][nt][1] + bv2.y);
            dst[(size_t)(rr + 8) * 64 + wcol] = packbf(acc[mt][nt][2] + bv2.x, acc[mt][nt][3] + bv2.y);
        }
    }
}

// ---------------------------------------------------------------------------
// Kernel 2: flash attention, bf16 mma + ldmatrix (unchanged from R5).
// ---------------------------------------------------------------------------
#define KS_WSTR 20
#define KS_BSTR 80
#define VT_WOFF (QTOK * KS_WSTR)
#define VT_BOFF (QTOK * KS_BSTR)
#define VT_WSTR 196
#define VT_BSTR 784
#define K2_SMEM (VT_BOFF + 32 * VT_BSTR)

__global__ __launch_bounds__(384, 2) void attn_mma()
{
    extern __shared__ uint32_t smw[];
    uint32_t sbase = (uint32_t)__cvta_generic_to_shared(smw);

    int bx   = blockIdx.x;
    int bl   = bx >> 3;
    int m    = (bx >> 1) & 3;
    int half = bx & 1;
    size_t base_w = (size_t)bl * QTOK * 64 + m * 16;

    int tid = threadIdx.x, warp = tid >> 5, lane = tid & 31;
    int g = lane >> 2, c = lane & 3;

    const float sc = 0.1767766952966369f * 1.4426950408889634f;

    for (int i = tid; i < QTOK * 16; i += 384) {
        int row = i >> 4, w = i & 15;
        smw[row * KS_WSTR + w] = g_kp[base_w + (size_t)row * 64 + w];
    }
    for (int i = tid; i < (QTOK / 2) * 16; i += 384) {
        int r2 = i >> 4, w = i & 15;
        uint32_t u0 = g_vp[base_w + (size_t)(2 * r2)     * 64 + w];
        uint32_t u1 = g_vp[base_w + (size_t)(2 * r2 + 1) * 64 + w];
        smw[VT_WOFF + (2 * w)     * VT_WSTR + r2] = __byte_perm(u0, u1, 0x5410);
        smw[VT_WOFF + (2 * w + 1) * VT_WSTR + r2] = __byte_perm(u0, u1, 0x7632);
    }

    int q0 = half * 192 + warp * 16;
    uint32_t qa[2][4];
    {
        const uint32_t* qr0 = g_qp + base_w + (size_t)(q0 + g) * 64;
        const uint32_t* qr1 = g_qp + base_w + (size_t)(q0 + g + 8) * 64;
        #pragma unroll
        for (int kst = 0; kst < 2; ++kst) {
            qa[kst][0] = qr0[kst * 8 + c    ];
            qa[kst][1] = qr1[kst * 8 + c    ];
            qa[kst][2] = qr0[kst * 8 + c + 4];
            qa[kst][3] = qr1[kst * 8 + c + 4];
        }
    }
    __syncthreads();

    float o[4][4];
    #pragma unroll
    for (int nt = 0; nt < 4; ++nt)
        { o[nt][0]=0.f; o[nt][1]=0.f; o[nt][2]=0.f; o[nt][3]=0.f; }
    float mrun0 = -1e30f, mrun1 = -1e30f;
    float lrun0 = 0.f, lrun1 = 0.f;

    int rhi = (lane & 16) >> 1;
    uint32_t aK = sbase + ((lane & 7) + rhi) * KS_BSTR + (lane & 8) * 2;
    uint32_t aV = sbase + VT_BOFF + ((lane & 7) + rhi) * VT_BSTR + (lane & 8) * 2;

    for (int kc = 0; kc < QTOK; kc += 32) {
        float s[4][4];
        #pragma unroll
        for (int nt = 0; nt < 4; ++nt)
            { s[nt][0]=0.f; s[nt][1]=0.f; s[nt][2]=0.f; s[nt][3]=0.f; }

        #pragma unroll
        for (int kst = 0; kst < 2; ++kst) {
            uint32_t b0[4], b1[4];
            ldsm4(b0, aK + (kc)      * KS_BSTR + kst * 32);
            ldsm4(b1, aK + (kc + 16) * KS_BSTR + kst * 32);
            mma16(s[0], qa[kst], b0);     mma16(s[1], qa[kst], b0 + 2);
            mma16(s[2], qa[kst], b1);     mma16(s[3], qa[kst], b1 + 2);
        }
        #pragma unroll
        for (int nt = 0; nt < 4; ++nt) {
            s[nt][0] *= sc; s[nt][1] *= sc; s[nt][2] *= sc; s[nt][3] *= sc;
        }

        float cm0 = s[0][0], cm1 = s[0][2];
        #pragma unroll
        for (int nt = 0; nt < 4; ++nt) {
            cm0 = fmaxf(cm0, fmaxf(s[nt][0], s[nt][1]));
            cm1 = fmaxf(cm1, fmaxf(s[nt][2], s[nt][3]));
        }
        cm0 = fmaxf(cm0, __shfl_xor_sync(FULLMASK, cm0, 1));
        cm0 = fmaxf(cm0, __shfl_xor_sync(FULLMASK, cm0, 2));
        cm1 = fmaxf(cm1, __shfl_xor_sync(FULLMASK, cm1, 1));
        cm1 = fmaxf(cm1, __shfl_xor_sync(FULLMASK, cm1, 2));
        float mn0 = fmaxf(mrun0, cm0);
        float mn1 = fmaxf(mrun1, cm1);
        float f0 = exp2f(mrun0 - mn0);
        float f1 = exp2f(mrun1 - mn1);
        float rs0 = 0.f, rs1 = 0.f;
        #pragma unroll
        for (int nt = 0; nt < 4; ++nt) {
            s[nt][0] = exp2f(s[nt][0] - mn0);
            s[nt][1] = exp2f(s[nt][1] - mn0);
            s[nt][2] = exp2f(s[nt][2] - mn1);
            s[nt][3] = exp2f(s[nt][3] - mn1);
            rs0 += s[nt][0] + s[nt][1];
            rs1 += s[nt][2] + s[nt][3];
        }
        rs0 += __shfl_xor_sync(FULLMASK, rs0, 1);
        rs0 += __shfl_xor_sync(FULLMASK, rs0, 2);
        rs1 += __shfl_xor_sync(FULLMASK, rs1, 1);
        rs1 += __shfl_xor_sync(FULLMASK, rs1, 2);
        lrun0 = lrun0 * f0 + rs0;
        lrun1 = lrun1 * f1 + rs1;
        mrun0 = mn0; mrun1 = mn1;
        #pragma unroll
        for (int nt = 0; nt < 4; ++nt) {
            o[nt][0] *= f0; o[nt][1] *= f0;
            o[nt][2] *= f1; o[nt][3] *= f1;
        }

        #pragma unroll
        for (int kt = 0; kt < 2; ++kt) {
            uint32_t pa[4];
            pa[0] = packbf(s[2*kt  ][0], s[2*kt  ][1]);
            pa[1] = packbf(s[2*kt  ][2], s[2*kt  ][3]);
            pa[2] = packbf(s[2*kt+1][0], s[2*kt+1][1]);
            pa[3] = packbf(s[2*kt+1][2], s[2*kt+1][3]);
            int kbase = kc + kt * 16;
            uint32_t v0[4], v1[4];
            ldsm4(v0, aV                + kbase * 2);
            ldsm4(v1, aV + 16 * VT_BSTR + kbase * 2);
            mma16(o[0], pa, v0);     mma16(o[1], pa, v0 + 2);
            mma16(o[2], pa, v1);     mma16(o[3], pa, v1 + 2);
        }
    }

    float inv0 = 1.0f / lrun0;
    float inv1 = 1.0f / lrun1;
    int r0 = q0 + g;
    #pragma unroll
    for (int nt = 0; nt < 4; ++nt) {
        int wcol = nt * 4 + c;
        g_at[base_w + (size_t)r0 * 64 + wcol]       = packbf(o[nt][0] * inv0, o[nt][1] * inv0);
        g_at[base_w + (size_t)(r0 + 8) * 64 + wcol] = packbf(o[nt][2] * inv1, o[nt][3] * inv1);
    }
}

// ---------------------------------------------------------------------------
// Kernel 3: fused mean-over-views (bf16 in) + output projection + bias + skip.
// ---------------------------------------------------------------------------
__global__ __launch_bounds__(256) void out_proj_kernel(
    const float* __restrict__ wp, const float* __restrict__ bp,
    const float* __restrict__ skip, float* __restrict__ out)
{
    extern __shared__ float sm[];
    float* Xs = sm;                 // 64*128
    float* Ws = sm + 64 * 128;      // 128*128

    int tid  = threadIdx.x;
    int row0 = blockIdx.x * 64;

    for (int i = tid; i < 128 * 32; i += 256)
        ((float4*)Ws)[i] = ((const float4*)wp)[i];

    for (int i = tid; i < 64 * 32; i += 256) {
        int rloc = i >> 5, cq = i & 31;
        int r2 = row0 + rloc;
        int bl = r2 >> 6;
        int w  = r2 & 63;
        float4 a; a.x = 0.f; a.y = 0.f; a.z = 0.f; a.w = 0.f;
        #pragma unroll
        for (int n = 0; n < NVIEW; ++n) {
            const uint32_t* p = g_at + (size_t)(bl * QTOK + n * 64 + w) * 64 + cq * 2;
            uint32_t u0 = p[0], u1 = p[1];
            a.x += bflo(u0); a.y += bfhi(u0);
            a.z += bflo(u1); a.w += bfhi(u1);
        }
        const float invn = 1.0f / 6.0f;
        a.x *= invn; a.y *= invn; a.z *= invn; a.w *= invn;
        ((float4*)Xs)[rloc * 32 + cq] = a;
    }
    __syncthreads();

    int ti = tid >> 5;
    int cj = tid & 31;
    float acc[8][4];
    #pragma unroll
    for (int i = 0; i < 8; ++i) { acc[i][0]=0.f; acc[i][1]=0.f; acc[i][2]=0.f; acc[i][3]=0.f; }

    const float4* Ws4 = (const float4*)Ws;
    #pragma unroll 8
    for (int kk = 0; kk < 128; ++kk) {
        float4 wv = Ws4[kk * 32 + cj];
        #pragma unroll
        for (int i = 0; i < 8; ++i) {
            float xv = Xs[(ti * 8 + i) * 128 + kk];
            acc[i][0] += xv * wv.x;
            acc[i][1] += xv * wv.y;
            acc[i][2] += xv * wv.z;
            acc[i][3] += xv * wv.w;
        }
    }

    float4 bsv = ((const float4*)bp)[cj];
    #pragma unroll
    for (int i = 0; i < 8; ++i) {
        int r = row0 + ti * 8 + i;
        float4 sk = ((const float4*)(skip + (size_t)r * 128))[cj];
        float4 o;
        o.x = acc[i][0] + bsv.x + sk.x;
        o.y = acc[i][1] + bsv.y + sk.y;
        o.z = acc[i][2] + bsv.z + sk.z;
        o.w = acc[i][3] + bsv.w + sk.w;
        ((float4*)(out + (size_t)r * 128))[cj] = o;
    }
}

// ---------------------------------------------------------------------------
extern "C" void kernel_launch(void* const* d_in, const int* in_sizes, int n_in,
                              void* d_out, int out_size)
{
    const float* q     = (const float*)d_in[0];
    const float* k     = (const float*)d_in[1];
    const float* v     = (const float*)d_in[2];
    const float* skip  = (const float*)d_in[3];
    const float* lnq_g = (const float*)d_in[4];
    const float* lnq_b = (const float*)d_in[5];
    const float* lnk_g = (const float*)d_in[6];
    const float* lnk_b = (const float*)d_in[7];
    const float* lnv_g = (const float*)d_in[8];
    const float* lnv_b = (const float*)d_in[9];
    const float* wq    = (const float*)d_in[10];
    const float* bq    = (const float*)d_in[11];
    const float* wk    = (const float*)d_in[12];
    const float* bk    = (const float*)d_in[13];
    const float* wv    = (const float*)d_in[14];
    const float* bv    = (const float*)d_in[15];
    const float* wp    = (const float*)d_in[16];
    const float* bp    = (const float*)d_in[17];
    float* out = (float*)d_out;

    cudaFuncSetAttribute(ln_proj_mma,     cudaFuncAttributeMaxDynamicSharedMemorySize, K1_SMEM);
    cudaFuncSetAttribute(attn_mma,        cudaFuncAttributeMaxDynamicSharedMemorySize, K2_SMEM);
    cudaFuncSetAttribute(out_proj_kernel, cudaFuncAttributeMaxDynamicSharedMemorySize, 96 * 1024);

    pack_w_kernel<<<3, 256>>>(wq, wk, wv);

    ln_proj_mma<<<dim3(TOKENS / 64, 3), 256, K1_SMEM>>>(
        q, k, v, lnq_g, lnq_b, lnk_g, lnk_b, lnv_g, lnv_b, bq, bk, bv);

    attn_mma<<<NBL * HEADS * 2, 384, K2_SMEM>>>();

    out_proj_kernel<<<R2ROWS / 64, 256, 96 * 1024>>>(wp, bp, skip, out);
}

// round 7
// speedup vs baseline: 4.3962x; 1.0630x over previous
#include <cuda_runtime.h>
#include <cstdint>

// Problem constants
#define BATCH   2
#define NVIEW   6
#define XD      8
#define YD      8
#define W1D     8
#define W2D     8
#define DIM     128
#define HEADS   4
#define DHEAD   32
#define HDIM    128
#define LWIN    64
#define QTOK    384
#define NBL     128
#define TOKENS  49152
#define R2ROWS  8192
#define EPS     1e-5f
#define FULLMASK 0xffffffffu

// Scratch: bf16 intermediates packed as uint32 (2 bf16/word, 64 words/row)
__device__ uint32_t g_qp[TOKENS * 64];
__device__ uint32_t g_kp[TOKENS * 64];
__device__ uint32_t g_vp[TOKENS * 64];
__device__ uint32_t g_at[TOKENS * 64];
// Pre-packed transposed weights: [mat][n*64 + k2] = {W[2k2][n], W[2k2+1][n]} bf16x2
// mat 0..2 = wq,wk,wv (for ln_proj); mat 3 = wp (for out_proj)
__device__ uint32_t g_wt[4 * 128 * 64];

__device__ __forceinline__ uint32_t packbf(float lo, float hi) {
    uint32_t d;
    asm("cvt.rn.bf16x2.f32 %0, %1, %2;" : "=r"(d) : "f"(hi), "f"(lo));
    return d;
}
__device__ __forceinline__ float bflo(uint32_t u) { return __uint_as_float(u << 16); }
__device__ __forceinline__ float bfhi(uint32_t u) { return __uint_as_float(u & 0xffff0000u); }

// D += A(16x16) * B(16x8), bf16 inputs, fp32 accum
__device__ __forceinline__ void mma16(float* d, const uint32_t* a, const uint32_t* b) {
    asm volatile("mma.sync.aligned.m16n8k16.row.col.f32.bf16.bf16.f32 "
        "{%0,%1,%2,%3}, {%4,%5,%6,%7}, {%8,%9}, {%0,%1,%2,%3};"
        : "+f"(d[0]), "+f"(d[1]), "+f"(d[2]), "+f"(d[3])
        : "r"(a[0]), "r"(a[1]), "r"(a[2]), "r"(a[3]), "r"(b[0]), "r"(b[1]));
}
__device__ __forceinline__ void ldsm4(uint32_t* r, uint32_t saddr) {
    asm volatile("ldmatrix.sync.aligned.m8n8.x4.shared.b16 {%0,%1,%2,%3}, [%4];"
        : "=r"(r[0]), "=r"(r[1]), "=r"(r[2]), "=r"(r[3]) : "r"(saddr));
}

// ---------------------------------------------------------------------------
// Kernel 0: pre-pack the four weight matrices (runs once/launch).
// ---------------------------------------------------------------------------
__global__ __launch_bounds__(256) void pack_w_kernel(
    const float* __restrict__ wq, const float* __restrict__ wk,
    const float* __restrict__ wv, const float* __restrict__ wp)
{
    const float* W = (blockIdx.x == 0) ? wq : (blockIdx.x == 1) ? wk
                   : (blockIdx.x == 2) ? wv : wp;
    uint32_t* dst = g_wt + blockIdx.x * 8192;
    for (int i = threadIdx.x; i < 8192; i += 256) {
        int k2 = i >> 7, n = i & 127;
        dst[n * 64 + k2] = packbf(W[(2 * k2) * 128 + n], W[(2 * k2 + 1) * 128 + n]);
    }
}

// ---------------------------------------------------------------------------
// Kernel 1: fold + LayerNorm + projection GEMM (bf16 mma + ldmatrix).
// ---------------------------------------------------------------------------
#define XS_WSTR 68
#define XS_BSTR 272
#define WT_WOFF (64 * XS_WSTR)
#define WT_BOFF (64 * XS_BSTR)
#define K1_SMEM ((64 + 128) * XS_BSTR)

__global__ __launch_bounds__(256, 3) void ln_proj_mma(
    const float* __restrict__ q, const float* __restrict__ k, const float* __restrict__ v,
    const float* __restrict__ lnq_g, const float* __restrict__ lnq_b,
    const float* __restrict__ lnk_g, const float* __restrict__ lnk_b,
    const float* __restrict__ lnv_g, const float* __restrict__ lnv_b,
    const float* __restrict__ bq, const float* __restrict__ bk,
    const float* __restrict__ bv)
{
    extern __shared__ uint32_t smw[];
    uint32_t sbase = (uint32_t)__cvta_generic_to_shared(smw);

    const float* src; const float* gam; const float* bet;
    const float* bias; uint32_t* dst;
    int mat = blockIdx.y;
    if (mat == 0)      { src = q; gam = lnq_g; bet = lnq_b; bias = bq; dst = g_qp; }
    else if (mat == 1) { src = k; gam = lnk_g; bet = lnk_b; bias = bk; dst = g_kp; }
    else               { src = v; gam = lnv_g; bet = lnv_b; bias = bv; dst = g_vp; }

    int tid  = threadIdx.x;
    int warp = tid >> 5;
    int lane = tid & 31;
    int row0 = blockIdx.x * 64;

    // Wt fill from pre-packed gmem
    {
        const uint4* wsrc = (const uint4*)(g_wt + mat * 8192);
        #pragma unroll
        for (int it = 0; it < 8; ++it) {
            int j  = it * 256 + tid;
            int n  = j >> 4, c4 = j & 15;
            *(uint4*)(smw + WT_WOFF + n * XS_WSTR + c4 * 4) = wsrc[j];
        }
    }

    // Hoisted fold decode: tile = fixed (b,l,n), contiguous 64x128 source block
    int bIdx = row0 / (LWIN * QTOK);
    int rem  = row0 % (LWIN * QTOK);
    int l = rem / QTOK;
    int t = rem % QTOK;
    int n = t >> 6;
    int x = l >> 3, y = l & 7;
    const float* srcBase = src +
        (size_t)((((bIdx * NVIEW + n) * XD + x) * YD + y)) * (W1D * W2D * DIM);

    // LayerNorm 64 tokens: warp per token, contiguous rows
    float4 gg  = ((const float4*)gam)[lane];
    float4 bb4 = ((const float4*)bet)[lane];
    #pragma unroll
    for (int it = 0; it < 8; ++it) {
        int rloc = it * 8 + warp;
        float4 xv = ((const float4*)(srcBase + rloc * DIM))[lane];
        float s  = xv.x + xv.y + xv.z + xv.w;
        float ss = xv.x * xv.x + xv.y * xv.y + xv.z * xv.z + xv.w * xv.w;
        #pragma unroll
        for (int o = 16; o; o >>= 1) {
            s  += __shfl_xor_sync(FULLMASK, s,  o);
            ss += __shfl_xor_sync(FULLMASK, ss, o);
        }
        float mu  = s * (1.0f / 128.0f);
        float var = ss * (1.0f / 128.0f) - mu * mu;
        float rs  = rsqrtf(var + EPS);
        float o0 = (xv.x - mu) * rs * gg.x + bb4.x;
        float o1 = (xv.y - mu) * rs * gg.y + bb4.y;
        float o2 = (xv.z - mu) * rs * gg.z + bb4.z;
        float o3 = (xv.w - mu) * rs * gg.w + bb4.w;
        smw[rloc * XS_WSTR + lane * 2    ] = packbf(o0, o1);
        smw[rloc * XS_WSTR + lane * 2 + 1] = packbf(o2, o3);
    }
    __syncthreads();

    int mg = warp >> 2, ng = warp & 3;
    int g  = lane >> 2, c = lane & 3;

    float acc[2][4][4];
    #pragma unroll
    for (int mt = 0; mt < 2; ++mt)
        #pragma unroll
        for (int nt = 0; nt < 4; ++nt)
            { acc[mt][nt][0]=0.f; acc[mt][nt][1]=0.f; acc[mt][nt][2]=0.f; acc[mt][nt][3]=0.f; }

    int khi = (lane & 16) >> 1;
    uint32_t aA0 = sbase + (mg * 32 + (lane & 15)) * XS_BSTR + khi * 2;
    uint32_t aA1 = aA0 + 16 * XS_BSTR;
    uint32_t aB0 = sbase + WT_BOFF
                 + (ng * 32 + (lane & 7) + khi) * XS_BSTR + (lane & 8) * 2;
    uint32_t aB1 = aB0 + 16 * XS_BSTR;

    #pragma unroll
    for (int kst = 0; kst < 8; ++kst) {
        uint32_t a0[4], a1[4], b0[4], b1[4];
        ldsm4(a0, aA0 + kst * 32);
        ldsm4(a1, aA1 + kst * 32);
        ldsm4(b0, aB0 + kst * 32);
        ldsm4(b1, aB1 + kst * 32);
        mma16(acc[0][0], a0, b0);     mma16(acc[0][1], a0, b0 + 2);
        mma16(acc[0][2], a0, b1);     mma16(acc[0][3], a0, b1 + 2);
        mma16(acc[1][0], a1, b0);     mma16(acc[1][1], a1, b0 + 2);
        mma16(acc[1][2], a1, b1);     mma16(acc[1][3], a1, b1 + 2);
    }

    #pragma unroll
    for (int nt = 0; nt < 4; ++nt) {
        int col = ng * 32 + nt * 8 + c * 2;
        float2 bv2 = *(const float2*)(bias + col);
        int wcol = ng * 16 + nt * 4 + c;
        #pragma unroll
        for (int mt = 0; mt < 2; ++mt) {
            int rr = row0 + mg * 32 + mt * 16 + g;
            dst[(size_t)rr * 64 + wcol]       = packbf(acc[mt][nt][0] + bv2.x, acc[mt][nt][1] + bv2.y);
            dst[(size_t)(rr + 8) * 64 + wcol] = packbf(acc[mt][nt][2] + bv2.x, acc[mt][nt][3] + bv2.y);
        }
    }
}

// ---------------------------------------------------------------------------
// Kernel 2: flash attention, bf16 mma + ldmatrix (unchanged).
// ---------------------------------------------------------------------------
#define KS_WSTR 20
#define KS_BSTR 80
#define VT_WOFF (QTOK * KS_WSTR)
#define VT_BOFF (QTOK * KS_BSTR)
#define VT_WSTR 196
#define VT_BSTR 784
#define K2_SMEM (VT_BOFF + 32 * VT_BSTR)

__global__ __launch_bounds__(384, 2) void attn_mma()
{
    extern __shared__ uint32_t smw[];
    uint32_t sbase = (uint32_t)__cvta_generic_to_shared(smw);

    int bx   = blockIdx.x;
    int bl   = bx >> 3;
    int m    = (bx >> 1) & 3;
    int half = bx & 1;
    size_t base_w = (size_t)bl * QTOK * 64 + m * 16;

    int tid = threadIdx.x, warp = tid >> 5, lane = tid & 31;
    int g = lane >> 2, c = lane & 3;

    const float sc = 0.1767766952966369f * 1.4426950408889634f;

    for (int i = tid; i < QTOK * 16; i += 384) {
        int row = i >> 4, w = i & 15;
        smw[row * KS_WSTR + w] = g_kp[base_w + (size_t)row * 64 + w];
    }
    for (int i = tid; i < (QTOK / 2) * 16; i += 384) {
        int r2 = i >> 4, w = i & 15;
        uint32_t u0 = g_vp[base_w + (size_t)(2 * r2)     * 64 + w];
        uint32_t u1 = g_vp[base_w + (size_t)(2 * r2 + 1) * 64 + w];
        smw[VT_WOFF + (2 * w)     * VT_WSTR + r2] = __byte_perm(u0, u1, 0x5410);
        smw[VT_WOFF + (2 * w + 1) * VT_WSTR + r2] = __byte_perm(u0, u1, 0x7632);
    }

    int q0 = half * 192 + warp * 16;
    uint32_t qa[2][4];
    {
        const uint32_t* qr0 = g_qp + base_w + (size_t)(q0 + g) * 64;
        const uint32_t* qr1 = g_qp + base_w + (size_t)(q0 + g + 8) * 64;
        #pragma unroll
        for (int kst = 0; kst < 2; ++kst) {
            qa[kst][0] = qr0[kst * 8 + c    ];
            qa[kst][1] = qr1[kst * 8 + c    ];
            qa[kst][2] = qr0[kst * 8 + c + 4];
            qa[kst][3] = qr1[kst * 8 + c + 4];
        }
    }
    __syncthreads();

    float o[4][4];
    #pragma unroll
    for (int nt = 0; nt < 4; ++nt)
        { o[nt][0]=0.f; o[nt][1]=0.f; o[nt][2]=0.f; o[nt][3]=0.f; }
    float mrun0 = -1e30f, mrun1 = -1e30f;
    float lrun0 = 0.f, lrun1 = 0.f;

    int rhi = (lane & 16) >> 1;
    uint32_t aK = sbase + ((lane & 7) + rhi) * KS_BSTR + (lane & 8) * 2;
    uint32_t aV = sbase + VT_BOFF + ((lane & 7) + rhi) * VT_BSTR + (lane & 8) * 2;

    for (int kc = 0; kc < QTOK; kc += 32) {
        float s[4][4];
        #pragma unroll
        for (int nt = 0; nt < 4; ++nt)
            { s[nt][0]=0.f; s[nt][1]=0.f; s[nt][2]=0.f; s[nt][3]=0.f; }

        #pragma unroll
        for (int kst = 0; kst < 2; ++kst) {
            uint32_t b0[4], b1[4];
            ldsm4(b0, aK + (kc)      * KS_BSTR + kst * 32);
            ldsm4(b1, aK + (kc + 16) * KS_BSTR + kst * 32);
            mma16(s[0], qa[kst], b0);     mma16(s[1], qa[kst], b0 + 2);
            mma16(s[2], qa[kst], b1);     mma16(s[3], qa[kst], b1 + 2);
        }
        #pragma unroll
        for (int nt = 0; nt < 4; ++nt) {
            s[nt][0] *= sc; s[nt][1] *= sc; s[nt][2] *= sc; s[nt][3] *= sc;
        }

        float cm0 = s[0][0], cm1 = s[0][2];
        #pragma unroll
        for (int nt = 0; nt < 4; ++nt) {
            cm0 = fmaxf(cm0, fmaxf(s[nt][0], s[nt][1]));
            cm1 = fmaxf(cm1, fmaxf(s[nt][2], s[nt][3]));
        }
        cm0 = fmaxf(cm0, __shfl_xor_sync(FULLMASK, cm0, 1));
        cm0 = fmaxf(cm0, __shfl_xor_sync(FULLMASK, cm0, 2));
        cm1 = fmaxf(cm1, __shfl_xor_sync(FULLMASK, cm1, 1));
        cm1 = fmaxf(cm1, __shfl_xor_sync(FULLMASK, cm1, 2));
        float mn0 = fmaxf(mrun0, cm0);
        float mn1 = fmaxf(mrun1, cm1);
        float f0 = exp2f(mrun0 - mn0);
        float f1 = exp2f(mrun1 - mn1);
        float rs0 = 0.f, rs1 = 0.f;
        #pragma unroll
        for (int nt = 0; nt < 4; ++nt) {
            s[nt][0] = exp2f(s[nt][0] - mn0);
            s[nt][1] = exp2f(s[nt][1] - mn0);
            s[nt][2] = exp2f(s[nt][2] - mn1);
            s[nt][3] = exp2f(s[nt][3] - mn1);
            rs0 += s[nt][0] + s[nt][1];
            rs1 += s[nt][2] + s[nt][3];
        }
        rs0 += __shfl_xor_sync(FULLMASK, rs0, 1);
        rs0 += __shfl_xor_sync(FULLMASK, rs0, 2);
        rs1 += __shfl_xor_sync(FULLMASK, rs1, 1);
        rs1 += __shfl_xor_sync(FULLMASK, rs1, 2);
        lrun0 = lrun0 * f0 + rs0;
        lrun1 = lrun1 * f1 + rs1;
        mrun0 = mn0; mrun1 = mn1;
        #pragma unroll
        for (int nt = 0; nt < 4; ++nt) {
            o[nt][0] *= f0; o[nt][1] *= f0;
            o[nt][2] *= f1; o[nt][3] *= f1;
        }

        #pragma unroll
        for (int kt = 0; kt < 2; ++kt) {
            uint32_t pa[4];
            pa[0] = packbf(s[2*kt  ][0], s[2*kt  ][1]);
            pa[1] = packbf(s[2*kt  ][2], s[2*kt  ][3]);
            pa[2] = packbf(s[2*kt+1][0], s[2*kt+1][1]);
            pa[3] = packbf(s[2*kt+1][2], s[2*kt+1][3]);
            int kbase = kc + kt * 16;
            uint32_t v0[4], v1[4];
            ldsm4(v0, aV                + kbase * 2);
            ldsm4(v1, aV + 16 * VT_BSTR + kbase * 2);
            mma16(o[0], pa, v0);     mma16(o[1], pa, v0 + 2);
            mma16(o[2], pa, v1);     mma16(o[3], pa, v1 + 2);
        }
    }

    float inv0 = 1.0f / lrun0;
    float inv1 = 1.0f / lrun1;
    int r0 = q0 + g;
    #pragma unroll
    for (int nt = 0; nt < 4; ++nt) {
        int wcol = nt * 4 + c;
        g_at[base_w + (size_t)r0 * 64 + wcol]       = packbf(o[nt][0] * inv0, o[nt][1] * inv0);
        g_at[base_w + (size_t)(r0 + 8) * 64 + wcol] = packbf(o[nt][2] * inv1, o[nt][3] * inv1);
    }
}

// ---------------------------------------------------------------------------
// Kernel 3: mean-over-views + output projection (bf16 mma) + bias + skip.
// grid = 256 (32-row tiles), block = 128 (4 warps, each 32 rows x 32 cols).
// smem: Xs 32 x 136 bf16 + Wt 128 x 136 bf16 = 43520 B.
// ---------------------------------------------------------------------------
#define WT3_WOFF (32 * XS_WSTR)
#define WT3_BOFF (32 * XS_BSTR)
#define K3_SMEM ((32 + 128) * XS_BSTR)

__global__ __launch_bounds__(128) void out_proj_mma(
    const float* __restrict__ bp,
    const float* __restrict__ skip, float* __restrict__ out)
{
    extern __shared__ uint32_t smw[];
    uint32_t sbase = (uint32_t)__cvta_generic_to_shared(smw);

    int tid  = threadIdx.x;
    int warp = tid >> 5;
    int lane = tid & 31;
    int row0 = blockIdx.x * 32;

    // Wt fill from pre-packed gmem (wp = slot 3): 2048 uint4
    {
        const uint4* wsrc = (const uint4*)(g_wt + 3 * 8192);
        #pragma unroll
        for (int it = 0; it < 16; ++it) {
            int j  = it * 128 + tid;
            int n  = j >> 4, c4 = j & 15;
            *(uint4*)(smw + WT3_WOFF + n * XS_WSTR + c4 * 4) = wsrc[j];
        }
    }

    // Xs = mean over n of attention output, packed bf16
    // rows r2 = row0+rloc: bl = r2>>6, wr = r2&63; src row = bl*384 + n*64 + wr
    for (int i = tid; i < 32 * 64; i += 128) {
        int rloc = i >> 6, w = i & 63;
        int r2 = row0 + rloc;
        int bl = r2 >> 6;
        int wr = r2 & 63;
        const uint32_t* srcp = g_at + (size_t)(bl * QTOK + wr) * 64 + w;
        float a0 = 0.f, a1 = 0.f;
        #pragma unroll
        for (int n = 0; n < NVIEW; ++n) {
            uint32_t u = srcp[n * 64 * 64];
            a0 += bflo(u); a1 += bfhi(u);
        }
        smw[rloc * XS_WSTR + w] = packbf(a0 * (1.0f / 6.0f), a1 * (1.0f / 6.0f));
    }
    __syncthreads();

    // GEMM: warp ng owns 32 rows x 32 cols
    int ng = warp;
    int g  = lane >> 2, c = lane & 3;

    float acc[2][4][4];
    #pragma unroll
    for (int mt = 0; mt < 2; ++mt)
        #pragma unroll
        for (int nt = 0; nt < 4; ++nt)
            { acc[mt][nt][0]=0.f; acc[mt][nt][1]=0.f; acc[mt][nt][2]=0.f; acc[mt][nt][3]=0.f; }

    int khi = (lane & 16) >> 1;
    uint32_t aA0 = sbase + (lane & 15) * XS_BSTR + khi * 2;
    uint32_t aA1 = aA0 + 16 * XS_BSTR;
    uint32_t aB0 = sbase + WT3_BOFF
                 + (ng * 32 + (lane & 7) + khi) * XS_BSTR + (lane & 8) * 2;
    uint32_t aB1 = aB0 + 16 * XS_BSTR;

    #pragma unroll
    for (int kst = 0; kst < 8; ++kst) {
        uint32_t a0[4], a1[4], b0[4], b1[4];
        ldsm4(a0, aA0 + kst * 32);
        ldsm4(a1, aA1 + kst * 32);
        ldsm4(b0, aB0 + kst * 32);
        ldsm4(b1, aB1 + kst * 32);
        mma16(acc[0][0], a0, b0);     mma16(acc[0][1], a0, b0 + 2);
        mma16(acc[0][2], a0, b1);     mma16(acc[0][3], a0, b1 + 2);
        mma16(acc[1][0], a1, b0);     mma16(acc[1][1], a1, b0 + 2);
        mma16(acc[1][2], a1, b1);     mma16(acc[1][3], a1, b1 + 2);
    }

    // Epilogue: + bias + skip, store fp32
    #pragma unroll
    for (int nt = 0; nt < 4; ++nt) {
        int col = ng * 32 + nt * 8 + c * 2;
        float2 bv2 = *(const float2*)(bp + col);
        #pragma unroll
        for (int mt = 0; mt < 2; ++mt) {
            int rr = row0 + mt * 16 + g;
            float2 sk0 = *(const float2*)(skip + (size_t)rr * 128 + col);
            float2 sk1 = *(const float2*)(skip + (size_t)(rr + 8) * 128 + col);
            float2 o0 = { acc[mt][nt][0] + bv2.x + sk0.x, acc[mt][nt][1] + bv2.y + sk0.y };
            float2 o1 = { acc[mt][nt][2] + bv2.x + sk1.x, acc[mt][nt][3] + bv2.y + sk1.y };
            *(float2*)(out + (size_t)rr * 128 + col)       = o0;
            *(float2*)(out + (size_t)(rr + 8) * 128 + col) = o1;
        }
    }
}

// ---------------------------------------------------------------------------
extern "C" void kernel_launch(void* const* d_in, const int* in_sizes, int n_in,
                              void* d_out, int out_size)
{
    const float* q     = (const float*)d_in[0];
    const float* k     = (const float*)d_in[1];
    const float* v     = (const float*)d_in[2];
    const float* skip  = (const float*)d_in[3];
    const float* lnq_g = (const float*)d_in[4];
    const float* lnq_b = (const float*)d_in[5];
    const float* lnk_g = (const float*)d_in[6];
    const float* lnk_b = (const float*)d_in[7];
    const float* lnv_g = (const float*)d_in[8];
    const float* lnv_b = (const float*)d_in[9];
    const float* wq    = (const float*)d_in[10];
    const float* bq    = (const float*)d_in[11];
    const float* wk    = (const float*)d_in[12];
    const float* bk    = (const float*)d_in[13];
    const float* wv    = (const float*)d_in[14];
    const float* bv    = (const float*)d_in[15];
    const float* wp    = (const float*)d_in[16];
    const float* bp    = (const float*)d_in[17];
    float* out = (float*)d_out;

    cudaFuncSetAttribute(ln_proj_mma,  cudaFuncAttributeMaxDynamicSharedMemorySize, K1_SMEM);
    cudaFuncSetAttribute(attn_mma,     cudaFuncAttributeMaxDynamicSharedMemorySize, K2_SMEM);
    cudaFuncSetAttribute(out_proj_mma, cudaFuncAttributeMaxDynamicSharedMemorySize, K3_SMEM);

    pack_w_kernel<<<4, 256>>>(wq, wk, wv, wp);

    ln_proj_mma<<<dim3(TOKENS / 64, 3), 256, K1_SMEM>>>(
        q, k, v, lnq_g, lnq_b, lnk_g, lnk_b, lnv_g, lnv_b, bq, bk, bv);

    attn_mma<<<NBL * HEADS * 2, 384, K2_SMEM>>>();

    out_proj_mma<<<R2ROWS / 32, 128, K3_SMEM>>>(bp, skip, out);
}

// round 8
// speedup vs baseline: 5.8373x; 1.3278x over previous
#include <cuda_runtime.h>
#include <cstdint>

// Problem constants
#define BATCH   2
#define NVIEW   6
#define XD      8
#define YD      8
#define W1D     8
#define W2D     8
#define DIM     128
#define HEADS   4
#define DHEAD   32
#define HDIM    128
#define LWIN    64
#define QTOK    384
#define NBL     128
#define TOKENS  49152
#define R2ROWS  8192
#define EPS     1e-5f
#define FULLMASK 0xffffffffu

// Scratch: bf16 intermediates packed as uint32 (2 bf16/word, 64 words/row)
__device__ uint32_t g_qp[TOKENS * 64];
__device__ uint32_t g_kp[TOKENS * 64];
__device__ uint32_t g_vp[TOKENS * 64];
__device__ uint32_t g_at[TOKENS * 64];
// Pre-packed transposed weights, 4 slots: wq,wk,wv,wp
__device__ uint32_t g_wt[4 * 128 * 64];

__device__ __forceinline__ uint32_t packbf(float lo, float hi) {
    uint32_t d;
    asm("cvt.rn.bf16x2.f32 %0, %1, %2;" : "=r"(d) : "f"(hi), "f"(lo));
    return d;
}
__device__ __forceinline__ float bflo(uint32_t u) { return __uint_as_float(u << 16); }
__device__ __forceinline__ float bfhi(uint32_t u) { return __uint_as_float(u & 0xffff0000u); }

__device__ __forceinline__ void mma16(float* d, const uint32_t* a, const uint32_t* b) {
    asm volatile("mma.sync.aligned.m16n8k16.row.col.f32.bf16.bf16.f32 "
        "{%0,%1,%2,%3}, {%4,%5,%6,%7}, {%8,%9}, {%0,%1,%2,%3};"
        : "+f"(d[0]), "+f"(d[1]), "+f"(d[2]), "+f"(d[3])
        : "r"(a[0]), "r"(a[1]), "r"(a[2]), "r"(a[3]), "r"(b[0]), "r"(b[1]));
}
__device__ __forceinline__ void ldsm4(uint32_t* r, uint32_t saddr) {
    asm volatile("ldmatrix.sync.aligned.m8n8.x4.shared.b16 {%0,%1,%2,%3}, [%4];"
        : "=r"(r[0]), "=r"(r[1]), "=r"(r[2]), "=r"(r[3]) : "r"(saddr));
}

// ---------------------------------------------------------------------------
// Kernel 0: pre-pack the four weight matrices.
// ---------------------------------------------------------------------------
__global__ __launch_bounds__(256) void pack_w_kernel(
    const float* __restrict__ wq, const float* __restrict__ wk,
    const float* __restrict__ wv, const float* __restrict__ wp)
{
    const float* W = (blockIdx.x == 0) ? wq : (blockIdx.x == 1) ? wk
                   : (blockIdx.x == 2) ? wv : wp;
    uint32_t* dst = g_wt + blockIdx.x * 8192;
    for (int i = threadIdx.x; i < 8192; i += 256) {
        int k2 = i >> 7, n = i & 127;
        dst[n * 64 + k2] = packbf(W[(2 * k2) * 128 + n], W[(2 * k2 + 1) * 128 + n]);
    }
}

// ---------------------------------------------------------------------------
// Kernel 1: fold + LayerNorm + projection GEMM (bf16 mma + ldmatrix).
// q output is pre-scaled by softmax scale * log2(e).
// ---------------------------------------------------------------------------
#define XS_WSTR 68
#define XS_BSTR 272
#define WT_WOFF (64 * XS_WSTR)
#define WT_BOFF (64 * XS_BSTR)
#define K1_SMEM ((64 + 128) * XS_BSTR)

__global__ __launch_bounds__(256, 3) void ln_proj_mma(
    const float* __restrict__ q, const float* __restrict__ k, const float* __restrict__ v,
    const float* __restrict__ lnq_g, const float* __restrict__ lnq_b,
    const float* __restrict__ lnk_g, const float* __restrict__ lnk_b,
    const float* __restrict__ lnv_g, const float* __restrict__ lnv_b,
    const float* __restrict__ bq, const float* __restrict__ bk,
    const float* __restrict__ bv)
{
    extern __shared__ uint32_t smw[];
    uint32_t sbase = (uint32_t)__cvta_generic_to_shared(smw);

    const float* src; const float* gam; const float* bet;
    const float* bias; uint32_t* dst;
    int mat = blockIdx.y;
    if (mat == 0)      { src = q; gam = lnq_g; bet = lnq_b; bias = bq; dst = g_qp; }
    else if (mat == 1) { src = k; gam = lnk_g; bet = lnk_b; bias = bk; dst = g_kp; }
    else               { src = v; gam = lnv_g; bet = lnv_b; bias = bv; dst = g_vp; }
    // fold softmax scale (in exp2 domain) into q
    const float qmul = (mat == 0) ? 0.1767766952966369f * 1.4426950408889634f : 1.0f;

    int tid  = threadIdx.x;
    int warp = tid >> 5;
    int lane = tid & 31;
    int row0 = blockIdx.x * 64;

    // Wt fill from pre-packed gmem
    {
        const uint4* wsrc = (const uint4*)(g_wt + mat * 8192);
        #pragma unroll
        for (int it = 0; it < 8; ++it) {
            int j  = it * 256 + tid;
            int n  = j >> 4, c4 = j & 15;
            *(uint4*)(smw + WT_WOFF + n * XS_WSTR + c4 * 4) = wsrc[j];
        }
    }

    // Hoisted fold decode: tile = fixed (b,l,n), contiguous 64x128 source block
    int bIdx = row0 / (LWIN * QTOK);
    int rem  = row0 % (LWIN * QTOK);
    int l = rem / QTOK;
    int t = rem % QTOK;
    int n = t >> 6;
    int x = l >> 3, y = l & 7;
    const float* srcBase = src +
        (size_t)((((bIdx * NVIEW + n) * XD + x) * YD + y)) * (W1D * W2D * DIM);

    float4 gg  = ((const float4*)gam)[lane];
    float4 bb4 = ((const float4*)bet)[lane];
    #pragma unroll
    for (int it = 0; it < 8; ++it) {
        int rloc = it * 8 + warp;
        float4 xv = ((const float4*)(srcBase + rloc * DIM))[lane];
        float s  = xv.x + xv.y + xv.z + xv.w;
        float ss = xv.x * xv.x + xv.y * xv.y + xv.z * xv.z + xv.w * xv.w;
        #pragma unroll
        for (int o = 16; o; o >>= 1) {
            s  += __shfl_xor_sync(FULLMASK, s,  o);
            ss += __shfl_xor_sync(FULLMASK, ss, o);
        }
        float mu  = s * (1.0f / 128.0f);
        float var = ss * (1.0f / 128.0f) - mu * mu;
        float rs  = rsqrtf(var + EPS);
        float o0 = (xv.x - mu) * rs * gg.x + bb4.x;
        float o1 = (xv.y - mu) * rs * gg.y + bb4.y;
        float o2 = (xv.z - mu) * rs * gg.z + bb4.z;
        float o3 = (xv.w - mu) * rs * gg.w + bb4.w;
        smw[rloc * XS_WSTR + lane * 2    ] = packbf(o0, o1);
        smw[rloc * XS_WSTR + lane * 2 + 1] = packbf(o2, o3);
    }
    __syncthreads();

    int mg = warp >> 2, ng = warp & 3;
    int g  = lane >> 2, c = lane & 3;

    float acc[2][4][4];
    #pragma unroll
    for (int mt = 0; mt < 2; ++mt)
        #pragma unroll
        for (int nt = 0; nt < 4; ++nt)
            { acc[mt][nt][0]=0.f; acc[mt][nt][1]=0.f; acc[mt][nt][2]=0.f; acc[mt][nt][3]=0.f; }

    int khi = (lane & 16) >> 1;
    uint32_t aA0 = sbase + (mg * 32 + (lane & 15)) * XS_BSTR + khi * 2;
    uint32_t aA1 = aA0 + 16 * XS_BSTR;
    uint32_t aB0 = sbase + WT_BOFF
                 + (ng * 32 + (lane & 7) + khi) * XS_BSTR + (lane & 8) * 2;
    uint32_t aB1 = aB0 + 16 * XS_BSTR;

    #pragma unroll
    for (int kst = 0; kst < 8; ++kst) {
        uint32_t a0[4], a1[4], b0[4], b1[4];
        ldsm4(a0, aA0 + kst * 32);
        ldsm4(a1, aA1 + kst * 32);
        ldsm4(b0, aB0 + kst * 32);
        ldsm4(b1, aB1 + kst * 32);
        mma16(acc[0][0], a0, b0);     mma16(acc[0][1], a0, b0 + 2);
        mma16(acc[0][2], a0, b1);     mma16(acc[0][3], a0, b1 + 2);
        mma16(acc[1][0], a1, b0);     mma16(acc[1][1], a1, b0 + 2);
        mma16(acc[1][2], a1, b1);     mma16(acc[1][3], a1, b1 + 2);
    }

    #pragma unroll
    for (int nt = 0; nt < 4; ++nt) {
        int col = ng * 32 + nt * 8 + c * 2;
        float2 bv2 = *(const float2*)(bias + col);
        int wcol = ng * 16 + nt * 4 + c;
        #pragma unroll
        for (int mt = 0; mt < 2; ++mt) {
            int rr = row0 + mg * 32 + mt * 16 + g;
            dst[(size_t)rr * 64 + wcol] =
                packbf((acc[mt][nt][0] + bv2.x) * qmul, (acc[mt][nt][1] + bv2.y) * qmul);
            dst[(size_t)(rr + 8) * 64 + wcol] =
                packbf((acc[mt][nt][2] + bv2.x) * qmul, (acc[mt][nt][3] + bv2.y) * qmul);
        }
    }
}

// ---------------------------------------------------------------------------
// Kernel 2: flash attention, bf16 mma + ldmatrix. No online max (values are
// LN-bounded; exp2 domain is safe), l reduced once after the loop.
// ---------------------------------------------------------------------------
#define KS_WSTR 20
#define KS_BSTR 80
#define VT_WOFF (QTOK * KS_WSTR)
#define VT_BOFF (QTOK * KS_BSTR)
#define VT_WSTR 196
#define VT_BSTR 784
#define K2_SMEM (VT_BOFF + 32 * VT_BSTR)

__global__ __launch_bounds__(384, 2) void attn_mma()
{
    extern __shared__ uint32_t smw[];
    uint32_t sbase = (uint32_t)__cvta_generic_to_shared(smw);

    int bx   = blockIdx.x;
    int bl   = bx >> 3;
    int m    = (bx >> 1) & 3;
    int half = bx & 1;
    size_t base_w = (size_t)bl * QTOK * 64 + m * 16;

    int tid = threadIdx.x, warp = tid >> 5, lane = tid & 31;
    int g = lane >> 2, c = lane & 3;

    // K fill: uint4 (4 words) per op; row stride 80 B is 16B-aligned
    for (int i = tid; i < QTOK * 4; i += 384) {
        int row = i >> 2, c4 = i & 3;
        uint4 u = ((const uint4*)(g_kp + base_w + (size_t)row * 64))[c4];
        *(uint4*)(smw + row * KS_WSTR + c4 * 4) = u;
    }
    // Vt fill: key-pair pack via byte_perm, uint4 source loads
    for (int i = tid; i < (QTOK / 2) * 4; i += 384) {
        int r2 = i >> 2, c4 = i & 3;
        uint4 u0 = ((const uint4*)(g_vp + base_w + (size_t)(2 * r2)     * 64))[c4];
        uint4 u1 = ((const uint4*)(g_vp + base_w + (size_t)(2 * r2 + 1) * 64))[c4];
        int w0 = c4 * 4;
        smw[VT_WOFF + (2*w0    ) * VT_WSTR + r2] = __byte_perm(u0.x, u1.x, 0x5410);
        smw[VT_WOFF + (2*w0 + 1) * VT_WSTR + r2] = __byte_perm(u0.x, u1.x, 0x7632);
        smw[VT_WOFF + (2*w0 + 2) * VT_WSTR + r2] = __byte_perm(u0.y, u1.y, 0x5410);
        smw[VT_WOFF + (2*w0 + 3) * VT_WSTR + r2] = __byte_perm(u0.y, u1.y, 0x7632);
        smw[VT_WOFF + (2*w0 + 4) * VT_WSTR + r2] = __byte_perm(u0.z, u1.z, 0x5410);
        smw[VT_WOFF + (2*w0 + 5) * VT_WSTR + r2] = __byte_perm(u0.z, u1.z, 0x7632);
        smw[VT_WOFF + (2*w0 + 6) * VT_WSTR + r2] = __byte_perm(u0.w, u1.w, 0x5410);
        smw[VT_WOFF + (2*w0 + 7) * VT_WSTR + r2] = __byte_perm(u0.w, u1.w, 0x7632);
    }

    // Q fragments straight from gmem (pre-scaled in k1)
    int q0 = half * 192 + warp * 16;
    uint32_t qa[2][4];
    {
        const uint32_t* qr0 = g_qp + base_w + (size_t)(q0 + g) * 64;
        const uint32_t* qr1 = g_qp + base_w + (size_t)(q0 + g + 8) * 64;
        #pragma unroll
        for (int kst = 0; kst < 2; ++kst) {
            qa[kst][0] = qr0[kst * 8 + c    ];
            qa[kst][1] = qr1[kst * 8 + c    ];
            qa[kst][2] = qr0[kst * 8 + c + 4];
            qa[kst][3] = qr1[kst * 8 + c + 4];
        }
    }
    __syncthreads();

    float o[4][4];
    #pragma unroll
    for (int nt = 0; nt < 4; ++nt)
        { o[nt][0]=0.f; o[nt][1]=0.f; o[nt][2]=0.f; o[nt][3]=0.f; }
    float lp0 = 0.f, lp1 = 0.f;   // per-thread partial row sums

    int rhi = (lane & 16) >> 1;
    uint32_t aK = sbase + ((lane & 7) + rhi) * KS_BSTR + (lane & 8) * 2;
    uint32_t aV = sbase + VT_BOFF + ((lane & 7) + rhi) * VT_BSTR + (lane & 8) * 2;

    for (int kc = 0; kc < QTOK; kc += 32) {
        float s[4][4];
        #pragma unroll
        for (int nt = 0; nt < 4; ++nt)
            { s[nt][0]=0.f; s[nt][1]=0.f; s[nt][2]=0.f; s[nt][3]=0.f; }

        #pragma unroll
        for (int kst = 0; kst < 2; ++kst) {
            uint32_t b0[4], b1[4];
            ldsm4(b0, aK + (kc)      * KS_BSTR + kst * 32);
            ldsm4(b1, aK + (kc + 16) * KS_BSTR + kst * 32);
            mma16(s[0], qa[kst], b0);     mma16(s[1], qa[kst], b0 + 2);
            mma16(s[2], qa[kst], b1);     mma16(s[3], qa[kst], b1 + 2);
        }

        // p = exp2(s); accumulate partial l; no max, no rescale
        #pragma unroll
        for (int nt = 0; nt < 4; ++nt) {
            s[nt][0] = exp2f(s[nt][0]);
            s[nt][1] = exp2f(s[nt][1]);
            s[nt][2] = exp2f(s[nt][2]);
            s[nt][3] = exp2f(s[nt][3]);
            lp0 += s[nt][0] + s[nt][1];
            lp1 += s[nt][2] + s[nt][3];
        }

        // O += P V
        #pragma unroll
        for (int kt = 0; kt < 2; ++kt) {
            uint32_t pa[4];
            pa[0] = packbf(s[2*kt  ][0], s[2*kt  ][1]);
            pa[1] = packbf(s[2*kt  ][2], s[2*kt  ][3]);
            pa[2] = packbf(s[2*kt+1][0], s[2*kt+1][1]);
            pa[3] = packbf(s[2*kt+1][2], s[2*kt+1][3]);
            int kbase = kc + kt * 16;
            uint32_t v0[4], v1[4];
            ldsm4(v0, aV                + kbase * 2);
            ldsm4(v1, aV + 16 * VT_BSTR + kbase * 2);
            mma16(o[0], pa, v0);     mma16(o[1], pa, v0 + 2);
            mma16(o[2], pa, v1);     mma16(o[3], pa, v1 + 2);
        }
    }

    // Row-sum reduce across the quad, once
    lp0 += __shfl_xor_sync(FULLMASK, lp0, 1);
    lp0 += __shfl_xor_sync(FULLMASK, lp0, 2);
    lp1 += __shfl_xor_sync(FULLMASK, lp1, 1);
    lp1 += __shfl_xor_sync(FULLMASK, lp1, 2);

    float inv0 = 1.0f / lp0;
    float inv1 = 1.0f / lp1;
    int r0 = q0 + g;
    #pragma unroll
    for (int nt = 0; nt < 4; ++nt) {
        int wcol = nt * 4 + c;
        g_at[base_w + (size_t)r0 * 64 + wcol]       = packbf(o[nt][0] * inv0, o[nt][1] * inv0);
        g_at[base_w + (size_t)(r0 + 8) * 64 + wcol] = packbf(o[nt][2] * inv1, o[nt][3] * inv1);
    }
}

// ---------------------------------------------------------------------------
// Kernel 3: mean-over-views + output projection (bf16 mma) + bias + skip.
// Mean-gather vectorized to uint4.
// ---------------------------------------------------------------------------
#define WT3_WOFF (32 * XS_WSTR)
#define WT3_BOFF (32 * XS_BSTR)
#define K3_SMEM ((32 + 128) * XS_BSTR)

__global__ __launch_bounds__(128) void out_proj_mma(
    const float* __restrict__ bp,
    const float* __restrict__ skip, float* __restrict__ out)
{
    extern __shared__ uint32_t smw[];
    uint32_t sbase = (uint32_t)__cvta_generic_to_shared(smw);

    int tid  = threadIdx.x;
    int warp = tid >> 5;
    int lane = tid & 31;
    int row0 = blockIdx.x * 32;

    {
        const uint4* wsrc = (const uint4*)(g_wt + 3 * 8192);
        #pragma unroll
        for (int it = 0; it < 16; ++it) {
            int j  = it * 128 + tid;
            int n  = j >> 4, c4 = j & 15;
            *(uint4*)(smw + WT3_WOFF + n * XS_WSTR + c4 * 4) = wsrc[j];
        }
    }

    // Xs = mean over n, uint4 loads (4 packed words = 8 bf16 per load)
    for (int i = tid; i < 32 * 16; i += 128) {
        int rloc = i >> 4, c4 = i & 15;
        int r2 = row0 + rloc;
        int bl = r2 >> 6;
        int wr = r2 & 63;
        const uint4* srcp = (const uint4*)(g_at + (size_t)(bl * QTOK + wr) * 64) + c4;
        float a0=0.f,a1=0.f,a2=0.f,a3=0.f,a4=0.f,a5=0.f,a6=0.f,a7=0.f;
        #pragma unroll
        for (int n = 0; n < NVIEW; ++n) {
            uint4 u = srcp[n * 64 * 16];
            a0 += bflo(u.x); a1 += bfhi(u.x);
            a2 += bflo(u.y); a3 += bfhi(u.y);
            a4 += bflo(u.z); a5 += bfhi(u.z);
            a6 += bflo(u.w); a7 += bfhi(u.w);
        }
        const float iv = 1.0f / 6.0f;
        uint4 ov;
        ov.x = packbf(a0 * iv, a1 * iv);
        ov.y = packbf(a2 * iv, a3 * iv);
        ov.z = packbf(a4 * iv, a5 * iv);
        ov.w = packbf(a6 * iv, a7 * iv);
        *(uint4*)(smw + rloc * XS_WSTR + c4 * 4) = ov;
    }
    __syncthreads();

    int ng = warp;
    int g  = lane >> 2, c = lane & 3;

    float acc[2][4][4];
    #pragma unroll
    for (int mt = 0; mt < 2; ++mt)
        #pragma unroll
        for (int nt = 0; nt < 4; ++nt)
            { acc[mt][nt][0]=0.f; acc[mt][nt][1]=0.f; acc[mt][nt][2]=0.f; acc[mt][nt][3]=0.f; }

    int khi = (lane & 16) >> 1;
    uint32_t aA0 = sbase + (lane & 15) * XS_BSTR + khi * 2;
    uint32_t aA1 = aA0 + 16 * XS_BSTR;
    uint32_t aB0 = sbase + WT3_BOFF
                 + (ng * 32 + (lane & 7) + khi) * XS_BSTR + (lane & 8) * 2;
    uint32_t aB1 = aB0 + 16 * XS_BSTR;

    #pragma unroll
    for (int kst = 0; kst < 8; ++kst) {
        uint32_t a0[4], a1[4], b0[4], b1[4];
        ldsm4(a0, aA0 + kst * 32);
        ldsm4(a1, aA1 + kst * 32);
        ldsm4(b0, aB0 + kst * 32);
        ldsm4(b1, aB1 + kst * 32);
        mma16(acc[0][0], a0, b0);     mma16(acc[0][1], a0, b0 + 2);
        mma16(acc[0][2], a0, b1);     mma16(acc[0][3], a0, b1 + 2);
        mma16(acc[1][0], a1, b0);     mma16(acc[1][1], a1, b0 + 2);
        mma16(acc[1][2], a1, b1);     mma16(acc[1][3], a1, b1 + 2);
    }

    #pragma unroll
    for (int nt = 0; nt < 4; ++nt) {
        int col = ng * 32 + nt * 8 + c * 2;
        float2 bv2 = *(const float2*)(bp + col);
        #pragma unroll
        for (int mt = 0; mt < 2; ++mt) {
            int rr = row0 + mt * 16 + g;
            float2 sk0 = *(const float2*)(skip + (size_t)rr * 128 + col);
            float2 sk1 = *(const float2*)(skip + (size_t)(rr + 8) * 128 + col);
            float2 o0 = { acc[mt][nt][0] + bv2.x + sk0.x, acc[mt][nt][1] + bv2.y + sk0.y };
            float2 o1 = { acc[mt][nt][2] + bv2.x + sk1.x, acc[mt][nt][3] + bv2.y + sk1.y };
            *(float2*)(out + (size_t)rr * 128 + col)       = o0;
            *(float2*)(out + (size_t)(rr + 8) * 128 + col) = o1;
        }
    }
}

// ---------------------------------------------------------------------------
extern "C" void kernel_launch(void* const* d_in, const int* in_sizes, int n_in,
                              void* d_out, int out_size)
{
    const float* q     = (const float*)d_in[0];
    const float* k     = (const float*)d_in[1];
    const float* v     = (const float*)d_in[2];
    const float* skip  = (const float*)d_in[3];
    const float* lnq_g = (const float*)d_in[4];
    const float* lnq_b = (const float*)d_in[5];
    const float* lnk_g = (const float*)d_in[6];
    const float* lnk_b = (const float*)d_in[7];
    const float* lnv_g = (const float*)d_in[8];
    const float* lnv_b = (const float*)d_in[9];
    const float* wq    = (const float*)d_in[10];
    const float* bq    = (const float*)d_in[11];
    const float* wk    = (const float*)d_in[12];
    const float* bk    = (const float*)d_in[13];
    const float* wv    = (const float*)d_in[14];
    const float* bv    = (const float*)d_in[15];
    const float* wp    = (const float*)d_in[16];
    const float* bp    = (const float*)d_in[17];
    float* out = (float*)d_out;

    cudaFuncSetAttribute(ln_proj_mma,  cudaFuncAttributeMaxDynamicSharedMemorySize, K1_SMEM);
    cudaFuncSetAttribute(attn_mma,     cudaFuncAttributeMaxDynamicSharedMemorySize, K2_SMEM);
    cudaFuncSetAttribute(out_proj_mma, cudaFuncAttributeMaxDynamicSharedMemorySize, K3_SMEM);

    pack_w_kernel<<<4, 256>>>(wq, wk, wv, wp);

    ln_proj_mma<<<dim3(TOKENS / 64, 3), 256, K1_SMEM>>>(
        q, k, v, lnq_g, lnq_b, lnk_g, lnk_b, lnv_g, lnv_b, bq, bk, bv);

    attn_mma<<<NBL * HEADS * 2, 384, K2_SMEM>>>();

    out_proj_mma<<<R2ROWS / 32, 128, K3_SMEM>>>(bp, skip, out);
}

// round 10
// speedup vs baseline: 5.9693x; 1.0226x over previous
#include <cuda_runtime.h>
#include <cstdint>

// Problem constants
#define BATCH   2
#define NVIEW   6
#define XD      8
#define YD      8
#define W1D     8
#define W2D     8
#define DIM     128
#define HEADS   4
#define DHEAD   32
#define HDIM    128
#define LWIN    64
#define QTOK    384
#define NBL     128
#define TOKENS  49152
#define R2ROWS  8192
#define EPS     1e-5f
#define FULLMASK 0xffffffffu

// Scratch: bf16 intermediates packed as uint32 (2 bf16/word, 64 words/row)
__device__ uint32_t g_qp[TOKENS * 64];
__device__ uint32_t g_kp[TOKENS * 64];
__device__ uint32_t g_vp[TOKENS * 64];
__device__ uint32_t g_at[TOKENS * 64];
// Pre-packed transposed weights, 4 slots: wq,wk,wv,wp
__device__ uint32_t g_wt[4 * 128 * 64];

__device__ __forceinline__ uint32_t packbf(float lo, float hi) {
    uint32_t d;
    asm("cvt.rn.bf16x2.f32 %0, %1, %2;" : "=r"(d) : "f"(hi), "f"(lo));
    return d;
}
__device__ __forceinline__ float bflo(uint32_t u) { return __uint_as_float(u << 16); }
__device__ __forceinline__ float bfhi(uint32_t u) { return __uint_as_float(u & 0xffff0000u); }

__device__ __forceinline__ void mma16(float* d, const uint32_t* a, const uint32_t* b) {
    asm volatile("mma.sync.aligned.m16n8k16.row.col.f32.bf16.bf16.f32 "
        "{%0,%1,%2,%3}, {%4,%5,%6,%7}, {%8,%9}, {%0,%1,%2,%3};"
        : "+f"(d[0]), "+f"(d[1]), "+f"(d[2]), "+f"(d[3])
        : "r"(a[0]), "r"(a[1]), "r"(a[2]), "r"(a[3]), "r"(b[0]), "r"(b[1]));
}
__device__ __forceinline__ void ldsm4(uint32_t* r, uint32_t saddr) {
    asm volatile("ldmatrix.sync.aligned.m8n8.x4.shared.b16 {%0,%1,%2,%3}, [%4];"
        : "=r"(r[0]), "=r"(r[1]), "=r"(r[2]), "=r"(r[3]) : "r"(saddr));
}

// ---------------------------------------------------------------------------
// Kernel 0: pre-pack weights. grid=64 (4 mats x 16 chunks), block=128.
// ---------------------------------------------------------------------------
__global__ __launch_bounds__(128) void pack_w_kernel(
    const float* __restrict__ wq, const float* __restrict__ wk,
    const float* __restrict__ wv, const float* __restrict__ wp)
{
    int mat   = blockIdx.x >> 4;
    int chunk = blockIdx.x & 15;
    const float* W = (mat == 0) ? wq : (mat == 1) ? wk : (mat == 2) ? wv : wp;
    uint32_t* dst = g_wt + mat * 8192;
    #pragma unroll
    for (int it = 0; it < 4; ++it) {
        int i = chunk * 512 + it * 128 + threadIdx.x;
        int k2 = i >> 7, n = i & 127;
        dst[n * 64 + k2] = packbf(W[(2 * k2) * 128 + n], W[(2 * k2 + 1) * 128 + n]);
    }
}

// ---------------------------------------------------------------------------
// Kernel 1: fold + LayerNorm (shfl butterfly) + projection GEMM (bf16 mma).
// q output pre-scaled by softmax scale * log2(e).
// ---------------------------------------------------------------------------
#define XS_WSTR 68
#define XS_BSTR 272
#define WT_WOFF (64 * XS_WSTR)
#define WT_BOFF (64 * XS_BSTR)
#define K1_SMEM ((64 + 128) * XS_BSTR)

__global__ __launch_bounds__(256, 3) void ln_proj_mma(
    const float* __restrict__ q, const float* __restrict__ k, const float* __restrict__ v,
    const float* __restrict__ lnq_g, const float* __restrict__ lnq_b,
    const float* __restrict__ lnk_g, const float* __restrict__ lnk_b,
    const float* __restrict__ lnv_g, const float* __restrict__ lnv_b,
    const float* __restrict__ bq, const float* __restrict__ bk,
    const float* __restrict__ bv)
{
    extern __shared__ uint32_t smw[];
    uint32_t sbase = (uint32_t)__cvta_generic_to_shared(smw);

    const float* src; const float* gam; const float* bet;
    const float* bias; uint32_t* dst;
    int mat = blockIdx.y;
    if (mat == 0)      { src = q; gam = lnq_g; bet = lnq_b; bias = bq; dst = g_qp; }
    else if (mat == 1) { src = k; gam = lnk_g; bet = lnk_b; bias = bk; dst = g_kp; }
    else               { src = v; gam = lnv_g; bet = lnv_b; bias = bv; dst = g_vp; }
    const float qmul = (mat == 0) ? 0.1767766952966369f * 1.4426950408889634f : 1.0f;

    int tid  = threadIdx.x;
    int warp = tid >> 5;
    int lane = tid & 31;
    int row0 = blockIdx.x * 64;

    // Wt fill from pre-packed gmem
    {
        const uint4* wsrc = (const uint4*)(g_wt + mat * 8192);
        #pragma unroll
        for (int it = 0; it < 8; ++it) {
            int j  = it * 256 + tid;
            int n  = j >> 4, c4 = j & 15;
            *(uint4*)(smw + WT_WOFF + n * XS_WSTR + c4 * 4) = wsrc[j];
        }
    }

    // Hoisted fold decode: tile = fixed (b,l,n), contiguous 64x128 source block
    int bIdx = row0 / (LWIN * QTOK);
    int rem  = row0 % (LWIN * QTOK);
    int l = rem / QTOK;
    int t = rem % QTOK;
    int n = t >> 6;
    int x = l >> 3, y = l & 7;
    const float* srcBase = src +
        (size_t)((((bIdx * NVIEW + n) * XD + x) * YD + y)) * (W1D * W2D * DIM);

    float4 gg  = ((const float4*)gam)[lane];
    float4 bb4 = ((const float4*)bet)[lane];
    #pragma unroll
    for (int it = 0; it < 8; ++it) {
        int rloc = it * 8 + warp;
        float4 xv = ((const float4*)(srcBase + rloc * DIM))[lane];
        float s  = xv.x + xv.y + xv.z + xv.w;
        float ss = xv.x * xv.x + xv.y * xv.y + xv.z * xv.z + xv.w * xv.w;
        #pragma unroll
        for (int o = 16; o; o >>= 1) {
            s  += __shfl_xor_sync(FULLMASK, s,  o);
            ss += __shfl_xor_sync(FULLMASK, ss, o);
        }
        float mu  = s * (1.0f / 128.0f);
        float var = ss * (1.0f / 128.0f) - mu * mu;
        float rs  = rsqrtf(var + EPS);
        float o0 = (xv.x - mu) * rs * gg.x + bb4.x;
        float o1 = (xv.y - mu) * rs * gg.y + bb4.y;
        float o2 = (xv.z - mu) * rs * gg.z + bb4.z;
        float o3 = (xv.w - mu) * rs * gg.w + bb4.w;
        smw[rloc * XS_WSTR + lane * 2    ] = packbf(o0, o1);
        smw[rloc * XS_WSTR + lane * 2 + 1] = packbf(o2, o3);
    }
    __syncthreads();

    int mg = warp >> 2, ng = warp & 3;
    int g  = lane >> 2, c = lane & 3;

    float acc[2][4][4];
    #pragma unroll
    for (int mt = 0; mt < 2; ++mt)
        #pragma unroll
        for (int nt = 0; nt < 4; ++nt)
            { acc[mt][nt][0]=0.f; acc[mt][nt][1]=0.f; acc[mt][nt][2]=0.f; acc[mt][nt][3]=0.f; }

    int khi = (lane & 16) >> 1;
    uint32_t aA0 = sbase + (mg * 32 + (lane & 15)) * XS_BSTR + khi * 2;
    uint32_t aA1 = aA0 + 16 * XS_BSTR;
    uint32_t aB0 = sbase + WT_BOFF
                 + (ng * 32 + (lane & 7) + khi) * XS_BSTR + (lane & 8) * 2;
    uint32_t aB1 = aB0 + 16 * XS_BSTR;

    #pragma unroll
    for (int kst = 0; kst < 8; ++kst) {
        uint32_t a0[4], a1[4], b0[4], b1[4];
        ldsm4(a0, aA0 + kst * 32);
        ldsm4(a1, aA1 + kst * 32);
        ldsm4(b0, aB0 + kst * 32);
        ldsm4(b1, aB1 + kst * 32);
        mma16(acc[0][0], a0, b0);     mma16(acc[0][1], a0, b0 + 2);
        mma16(acc[0][2], a0, b1);     mma16(acc[0][3], a0, b1 + 2);
        mma16(acc[1][0], a1, b0);     mma16(acc[1][1], a1, b0 + 2);
        mma16(acc[1][2], a1, b1);     mma16(acc[1][3], a1, b1 + 2);
    }

    #pragma unroll
    for (int nt = 0; nt < 4; ++nt) {
        int col = ng * 32 + nt * 8 + c * 2;
        float2 bv2 = *(const float2*)(bias + col);
        int wcol = ng * 16 + nt * 4 + c;
        #pragma unroll
        for (int mt = 0; mt < 2; ++mt) {
            int rr = row0 + mg * 32 + mt * 16 + g;
            dst[(size_t)rr * 64 + wcol] =
                packbf((acc[mt][nt][0] + bv2.x) * qmul, (acc[mt][nt][1] + bv2.y) * qmul);
            dst[(size_t)(rr + 8) * 64 + wcol] =
                packbf((acc[mt][nt][2] + bv2.x) * qmul, (acc[mt][nt][3] + bv2.y) * qmul);
        }
    }
}

// ---------------------------------------------------------------------------
// Kernel 2: flash attention. ONE CTA per (b,l,head): 768 threads, 24 warps
// x 16 q rows. No online max; l reduced once after the loop.
// ---------------------------------------------------------------------------
#define KS_WSTR 20
#define KS_BSTR 80
#define VT_WOFF (QTOK * KS_WSTR)
#define VT_BOFF (QTOK * KS_BSTR)
#define VT_WSTR 196
#define VT_BSTR 784
#define K2_SMEM (VT_BOFF + 32 * VT_BSTR)

__global__ __launch_bounds__(768, 1) void attn_mma()
{
    extern __shared__ uint32_t smw[];
    uint32_t sbase = (uint32_t)__cvta_generic_to_shared(smw);

    int bx = blockIdx.x;
    int bl = bx >> 2;
    int m  = bx & 3;
    size_t base_w = (size_t)bl * QTOK * 64 + m * 16;

    int tid = threadIdx.x, warp = tid >> 5, lane = tid & 31;
    int g = lane >> 2, c = lane & 3;

    // K fill: uint4 per op (1536 ops over 768 threads = 2 iters)
    #pragma unroll
    for (int it = 0; it < 2; ++it) {
        int i = it * 768 + tid;
        int row = i >> 2, c4 = i & 3;
        uint4 u = ((const uint4*)(g_kp + base_w + (size_t)row * 64))[c4];
        *(uint4*)(smw + row * KS_WSTR + c4 * 4) = u;
    }
    // Vt fill: key-pair pack via byte_perm (768 ops = 1 iter)
    {
        int i = tid;
        int r2 = i >> 2, c4 = i & 3;
        uint4 u0 = ((const uint4*)(g_vp + base_w + (size_t)(2 * r2)     * 64))[c4];
        uint4 u1 = ((const uint4*)(g_vp + base_w + (size_t)(2 * r2 + 1) * 64))[c4];
        int w0 = c4 * 4;
        smw[VT_WOFF + (2*w0    ) * VT_WSTR + r2] = __byte_perm(u0.x, u1.x, 0x5410);
        smw[VT_WOFF + (2*w0 + 1) * VT_WSTR + r2] = __byte_perm(u0.x, u1.x, 0x7632);
        smw[VT_WOFF + (2*w0 + 2) * VT_WSTR + r2] = __byte_perm(u0.y, u1.y, 0x5410);
        smw[VT_WOFF + (2*w0 + 3) * VT_WSTR + r2] = __byte_perm(u0.y, u1.y, 0x7632);
        smw[VT_WOFF + (2*w0 + 4) * VT_WSTR + r2] = __byte_perm(u0.z, u1.z, 0x5410);
        smw[VT_WOFF + (2*w0 + 5) * VT_WSTR + r2] = __byte_perm(u0.z, u1.z, 0x7632);
        smw[VT_WOFF + (2*w0 + 6) * VT_WSTR + r2] = __byte_perm(u0.w, u1.w, 0x5410);
        smw[VT_WOFF + (2*w0 + 7) * VT_WSTR + r2] = __byte_perm(u0.w, u1.w, 0x7632);
    }

    // Q fragments straight from gmem (pre-scaled in k1); 16 rows per warp
    int q0 = warp * 16;
    uint32_t qa[2][4];
    {
        const uint32_t* qr0 = g_qp + base_w + (size_t)(q0 + g) * 64;
        const uint32_t* qr1 = g_qp + base_w + (size_t)(q0 + g + 8) * 64;
        #pragma unroll
        for (int kst = 0; kst < 2; ++kst) {
            qa[kst][0] = qr0[kst * 8 + c    ];
            qa[kst][1] = qr1[kst * 8 + c    ];
            qa[kst][2] = qr0[kst * 8 + c + 4];
            qa[kst][3] = qr1[kst * 8 + c + 4];
        }
    }
    __syncthreads();

    float o[4][4];
    #pragma unroll
    for (int nt = 0; nt < 4; ++nt)
        { o[nt][0]=0.f; o[nt][1]=0.f; o[nt][2]=0.f; o[nt][3]=0.f; }
    float lp0 = 0.f, lp1 = 0.f;

    int rhi = (lane & 16) >> 1;
    uint32_t aK = sbase + ((lane & 7) + rhi) * KS_BSTR + (lane & 8) * 2;
    uint32_t aV = sbase + VT_BOFF + ((lane & 7) + rhi) * VT_BSTR + (lane & 8) * 2;

    for (int kc = 0; kc < QTOK; kc += 32) {
        float s[4][4];
        #pragma unroll
        for (int nt = 0; nt < 4; ++nt)
            { s[nt][0]=0.f; s[nt][1]=0.f; s[nt][2]=0.f; s[nt][3]=0.f; }

        #pragma unroll
        for (int kst = 0; kst < 2; ++kst) {
            uint32_t b0[4], b1[4];
            ldsm4(b0, aK + (kc)      * KS_BSTR + kst * 32);
            ldsm4(b1, aK + (kc + 16) * KS_BSTR + kst * 32);
            mma16(s[0], qa[kst], b0);     mma16(s[1], qa[kst], b0 + 2);
            mma16(s[2], qa[kst], b1);     mma16(s[3], qa[kst], b1 + 2);
        }

        #pragma unroll
        for (int nt = 0; nt < 4; ++nt) {
            s[nt][0] = exp2f(s[nt][0]);
            s[nt][1] = exp2f(s[nt][1]);
            s[nt][2] = exp2f(s[nt][2]);
            s[nt][3] = exp2f(s[nt][3]);
            lp0 += s[nt][0] + s[nt][1];
            lp1 += s[nt][2] + s[nt][3];
        }

        #pragma unroll
        for (int kt = 0; kt < 2; ++kt) {
            uint32_t pa[4];
            pa[0] = packbf(s[2*kt  ][0], s[2*kt  ][1]);
            pa[1] = packbf(s[2*kt  ][2], s[2*kt  ][3]);
            pa[2] = packbf(s[2*kt+1][0], s[2*kt+1][1]);
            pa[3] = packbf(s[2*kt+1][2], s[2*kt+1][3]);
            int kbase = kc + kt * 16;
            uint32_t v0[4], v1[4];
            ldsm4(v0, aV                + kbase * 2);
            ldsm4(v1, aV + 16 * VT_BSTR + kbase * 2);
            mma16(o[0], pa, v0);     mma16(o[1], pa, v0 + 2);
            mma16(o[2], pa, v1);     mma16(o[3], pa, v1 + 2);
        }
    }

    lp0 += __shfl_xor_sync(FULLMASK, lp0, 1);
    lp0 += __shfl_xor_sync(FULLMASK, lp0, 2);
    lp1 += __shfl_xor_sync(FULLMASK, lp1, 1);
    lp1 += __shfl_xor_sync(FULLMASK, lp1, 2);

    float inv0 = 1.0f / lp0;
    float inv1 = 1.0f / lp1;
    int r0 = q0 + g;
    #pragma unroll
    for (int nt = 0; nt < 4; ++nt) {
        int wcol = nt * 4 + c;
        g_at[base_w + (size_t)r0 * 64 + wcol]       = packbf(o[nt][0] * inv0, o[nt][1] * inv0);
        g_at[base_w + (size_t)(r0 + 8) * 64 + wcol] = packbf(o[nt][2] * inv1, o[nt][3] * inv1);
    }
}

// ---------------------------------------------------------------------------
// Kernel 3: mean-over-views + output projection (bf16 mma) + bias + skip.
// 16-row tiles, grid=512, block=128 (4 warps x 16x32 warp-tile).
// ---------------------------------------------------------------------------
#define WT3_WOFF (16 * XS_WSTR)
#define WT3_BOFF (16 * XS_BSTR)
#define K3_SMEM ((16 + 128) * XS_BSTR)

__global__ __launch_bounds__(128) void out_proj_mma(
    const float* __restrict__ bp,
    const float* __restrict__ skip, float* __restrict__ out)
{
    extern __shared__ uint32_t smw[];
    uint32_t sbase = (uint32_t)__cvta_generic_to_shared(smw);

    int tid  = threadIdx.x;
    int warp = tid >> 5;
    int lane = tid & 31;
    int row0 = blockIdx.x * 16;

    {
        const uint4* wsrc = (const uint4*)(g_wt + 3 * 8192);
        #pragma unroll
        for (int it = 0; it < 16; ++it) {
            int j  = it * 128 + tid;
            int n  = j >> 4, c4 = j & 15;
            *(uint4*)(smw + WT3_WOFF + n * XS_WSTR + c4 * 4) = wsrc[j];
        }
    }

    // Xs = mean over n, uint4 loads
    #pragma unroll
    for (int it = 0; it < 2; ++it) {
        int i = it * 128 + tid;
        int rloc = i >> 4, c4 = i & 15;
        int r2 = row0 + rloc;
        int bl = r2 >> 6;
        int wr = r2 & 63;
        const uint4* srcp = (const uint4*)(g_at + (size_t)(bl * QTOK + wr) * 64) + c4;
        float a0=0.f,a1=0.f,a2=0.f,a3=0.f,a4=0.f,a5=0.f,a6=0.f,a7=0.f;
        #pragma unroll
        for (int n = 0; n < NVIEW; ++n) {
            uint4 u = srcp[n * 64 * 16];
            a0 += bflo(u.x); a1 += bfhi(u.x);
            a2 += bflo(u.y); a3 += bfhi(u.y);
            a4 += bflo(u.z); a5 += bfhi(u.z);
            a6 += bflo(u.w); a7 += bfhi(u.w);
        }
        const float iv = 1.0f / 6.0f;
        uint4 ov;
        ov.x = packbf(a0 * iv, a1 * iv);
        ov.y = packbf(a2 * iv, a3 * iv);
        ov.z = packbf(a4 * iv, a5 * iv);
        ov.w = packbf(a6 * iv, a7 * iv);
        *(uint4*)(smw + rloc * XS_WSTR + c4 * 4) = ov;
    }
    __syncthreads();

    int ng = warp;
    int g  = lane >> 2, c = lane & 3;

    float acc[4][4];
    #pragma unroll
    for (int nt = 0; nt < 4; ++nt)
        { acc[nt][0]=0.f; acc[nt][1]=0.f; acc[nt][2]=0.f; acc[nt][3]=0.f; }

    int khi = (lane & 16) >> 1;
    uint32_t aA0 = sbase + (lane & 15) * XS_BSTR + khi * 2;
    uint32_t aB0 = sbase + WT3_BOFF
                 + (ng * 32 + (lane & 7) + khi) * XS_BSTR + (lane & 8) * 2;
    uint32_t aB1 = aB0 + 16 * XS_BSTR;

    #pragma unroll
    for (int kst = 0; kst < 8; ++kst) {
        uint32_t a0[4], b0[4], b1[4];
        ldsm4(a0, aA0 + kst * 32);
        ldsm4(b0, aB0 + kst * 32);
        ldsm4(b1, aB1 + kst * 32);
        mma16(acc[0], a0, b0);     mma16(acc[1], a0, b0 + 2);
        mma16(acc[2], a0, b1);     mma16(acc[3], a0, b1 + 2);
    }

    #pragma unroll
    for (int nt = 0; nt < 4; ++nt) {
        int col = ng * 32 + nt * 8 + c * 2;
        float2 bv2 = *(const float2*)(bp + col);
        int rr = row0 + g;
        float2 sk0 = *(const float2*)(skip + (size_t)rr * 128 + col);
        float2 sk1 = *(const float2*)(skip + (size_t)(rr + 8) * 128 + col);
        float2 o0 = { acc[nt][0] + bv2.x + sk0.x, acc[nt][1] + bv2.y + sk0.y };
        float2 o1 = { acc[nt][2] + bv2.x + sk1.x, acc[nt][3] + bv2.y + sk1.y };
        *(float2*)(out + (size_t)rr * 128 + col)       = o0;
        *(float2*)(out + (size_t)(rr + 8) * 128 + col) = o1;
    }
}

// ---------------------------------------------------------------------------
extern "C" void kernel_launch(void* const* d_in, const int* in_sizes, int n_in,
                              void* d_out, int out_size)
{
    const float* q     = (const float*)d_in[0];
    const float* k     = (const float*)d_in[1];
    const float* v     = (const float*)d_in[2];
    const float* skip  = (const float*)d_in[3];
    const float* lnq_g = (const float*)d_in[4];
    const float* lnq_b = (const float*)d_in[5];
    const float* lnk_g = (const float*)d_in[6];
    const float* lnk_b = (const float*)d_in[7];
    const float* lnv_g = (const float*)d_in[8];
    const float* lnv_b = (const float*)d_in[9];
    const float* wq    = (const float*)d_in[10];
    const float* bq    = (const float*)d_in[11];
    const float* wk    = (const float*)d_in[12];
    const float* bk    = (const float*)d_in[13];
    const float* wv    = (const float*)d_in[14];
    const float* bv    = (const float*)d_in[15];
    const float* wp    = (const float*)d_in[16];
    const float* bp    = (const float*)d_in[17];
    float* out = (float*)d_out;

    cudaFuncSetAttribute(ln_proj_mma,  cudaFuncAttributeMaxDynamicSharedMemorySize, K1_SMEM);
    cudaFuncSetAttribute(attn_mma,     cudaFuncAttributeMaxDynamicSharedMemorySize, K2_SMEM);
    cudaFuncSetAttribute(out_proj_mma, cudaFuncAttributeMaxDynamicSharedMemorySize, K3_SMEM);

    pack_w_kernel<<<64, 128>>>(wq, wk, wv, wp);

    ln_proj_mma<<<dim3(TOKENS / 64, 3), 256, K1_SMEM>>>(
        q, k, v, lnq_g, lnq_b, lnk_g, lnk_b, lnv_g, lnv_b, bq, bk, bv);

    attn_mma<<<NBL * HEADS, 768, K2_SMEM>>>();

    out_proj_mma<<<R2ROWS / 16, 128, K3_SMEM>>>(bp, skip, out);
}